// round 14
// baseline (speedup 1.0000x reference)
#include <cuda_runtime.h>
#include <cuda_bf16.h>
#include <math.h>
#include <stdint.h>

// Problem constants (fixed by the reference)
#define NN   10000            // nodes
#define NB   32               // batch
#define DIN  64
#define DOUT 64
#define FF   128              // DIN + DOUT
#define NE   160000           // edges
#define MM   (NN*NB)          // 320000 rows (node-major: m = n*32 + b)
#define V4F  1024             // float4 per node (full width)
#define V4H  512              // float4 per node (half width)
#define XPS  ((size_t)MM*FF)   // X plane elems per stage
#define HPS  ((size_t)MM*DOUT) // H plane elems per stage

typedef unsigned long long u64;
typedef unsigned int u32;

// ---------------- scratch (device globals; allocation-free) ----------------
__device__ __align__(16) float g_X[2][XPS];    // X0, X1 fp32 (conv operands)
__device__ __align__(16) float g_H[2][HPS];    // RH, D1 fp32 (conv operands)
__device__ __align__(16) float g_Z[HPS];       // update gate z
__device__ __align__(16) __nv_bfloat16 g_Xp[2][3][XPS];   // [hi/lo][stage]
__device__ __align__(16) __nv_bfloat16 g_Hp[2][3][HPS];
__device__ __align__(16) __nv_bfloat16 g_Wgp[2][128*384];
__device__ __align__(16) __nv_bfloat16 g_Wcp[2][64*384];
__device__ int    g_cnt[NN];
__device__ int    g_rs [NN+1];
__device__ int    g_cur[NN];
__device__ __align__(8) float2 g_epack[NE];   // {col as int bits, weight}

// ---------------- bf16 hi/lo split helpers ----------------
__device__ __forceinline__ unsigned packhi2(float a, float b, float& ra, float& rb) {
    __nv_bfloat16 ha = __float2bfloat16(a), hb = __float2bfloat16(b);
    ra = a - __bfloat162float(ha);
    rb = b - __bfloat162float(hb);
    __nv_bfloat162 t = __halves2bfloat162(ha, hb);
    return *reinterpret_cast<unsigned*>(&t);
}
__device__ __forceinline__ unsigned packlo2(float a, float b) {
    __nv_bfloat162 t = __floats2bfloat162_rn(a, b);
    return *reinterpret_cast<unsigned*>(&t);
}
__device__ __forceinline__ void emit_planes(float4 v, __nv_bfloat16* hp,
                                            __nv_bfloat16* lp, size_t po) {
    float r0, r1, r2, r3;
    unsigned h0 = packhi2(v.x, v.y, r0, r1);
    unsigned h1 = packhi2(v.z, v.w, r2, r3);
    *(uint2*)&hp[po] = make_uint2(h0, h1);
    *(uint2*)&lp[po] = make_uint2(packlo2(r0, r1), packlo2(r2, r3));
}

__device__ __forceinline__ u32 smem_u32(const void* p) {
    u32 a;
    asm("{ .reg .u64 t; cvta.to.shared.u64 t, %1; cvt.u32.u64 %0, t; }"
        : "=r"(a) : "l"(p));
    return a;
}
__device__ __forceinline__ void cpa16(u32 dst, const void* src) {
    asm volatile("cp.async.ca.shared.global [%0], [%1], 16;"
                 :: "r"(dst), "l"(src) : "memory");
}
#define CP_COMMIT() asm volatile("cp.async.commit_group;" ::: "memory")
#define CP_WAIT0()  asm volatile("cp.async.wait_group 0;"  ::: "memory")

// ldmatrix x4: four 8x8 bf16 fragments in one instruction (sm_75+ family PTX)
__device__ __forceinline__ void ldsm4(u32& r0, u32& r1, u32& r2, u32& r3, u32 addr) {
    asm volatile("ldmatrix.sync.aligned.m8n8.x4.shared.b16 {%0,%1,%2,%3}, [%4];"
        : "=r"(r0), "=r"(r1), "=r"(r2), "=r"(r3) : "r"(addr));
}

// mma.sync m16n8k16 row.col f32.bf16.bf16.f32 (family PTX, sm_80+)
__device__ __forceinline__ void mma_bf16(float* c,
        u32 a0, u32 a1, u32 a2, u32 a3, u32 b0, u32 b1) {
    asm volatile("mma.sync.aligned.m16n8k16.row.col.f32.bf16.bf16.f32 "
        "{%0,%1,%2,%3}, {%4,%5,%6,%7}, {%8,%9}, {%0,%1,%2,%3};"
        : "+f"(c[0]), "+f"(c[1]), "+f"(c[2]), "+f"(c[3])
        : "r"(a0), "r"(a1), "r"(a2), "r"(a3), "r"(b0), "r"(b1));
}

// ---------------- fast activations ----------------
__device__ __forceinline__ float fast_sigmoid(float g) {
    return __fdividef(1.f, 1.f + __expf(-g));
}
__device__ __forceinline__ float fast_tanh(float x) {
    float t = __expf(-2.f * fabsf(x));
    float r = __fdividef(1.f - t, 1.f + t);
    return copysignf(r, x);
}

// ---------------- kernel 1: histogram / build X0+planes / weight planes --------
#define HIST_BLKS (NE/256)     // 625
#define WPL_BLKS  64
__global__ void k_histbuild(const long long* __restrict__ ei64,
                            const float* __restrict__ in,
                            const float* __restrict__ hx,
                            const float* __restrict__ Wg,
                            const float* __restrict__ Wc) {
    if (blockIdx.x < HIST_BLKS) {
        __shared__ int bad;
        if (threadIdx.x == 0) bad = 0;
        __syncthreads();
        long long v = ei64[threadIdx.x];
        if (v < 0 || v >= NN) atomicOr(&bad, 1);
        __syncthreads();
        int e = blockIdx.x*256 + threadIdx.x;
        int r;
        if (bad) r = ((const int*)ei64)[e];
        else     r = (int)ei64[e];
        atomicAdd(&g_cnt[r], 1);
    } else if (blockIdx.x < HIST_BLKS + NN) {
        int n = blockIdx.x - HIST_BLKS;
        const float4* in4 = (const float4*)in;
        const float4* hx4 = (const float4*)hx;
        for (int i = threadIdx.x; i < 512; i += 256) {
            int b = i >> 4, f4 = i & 15;
            size_t m = (size_t)n*32 + b;
            size_t po = m*FF + f4*4;
            float4 v = __ldg(&in4[((size_t)b*NN + n)*16 + f4]);
            *(float4*)&g_X[0][po] = v;
            emit_planes(v, g_Xp[0][0], g_Xp[1][0], po);
            float4 w = __ldg(&hx4[((size_t)b*NN + n)*16 + f4]);
            *(float4*)&g_X[0][po + 64] = w;
            emit_planes(w, g_Xp[0][0], g_Xp[1][0], po + 64);
        }
    } else {
        int j = blockIdx.x - (HIST_BLKS + NN);
        for (int e = j*768 + threadIdx.x; e < (j+1)*768; e += 256) {
            float v = Wg[e];
            __nv_bfloat16 h = __float2bfloat16(v);
            g_Wgp[0][e] = h;
            g_Wgp[1][e] = __float2bfloat16(v - __bfloat162float(h));
        }
        for (int e = j*384 + threadIdx.x; e < (j+1)*384; e += 256) {
            float v = Wc[e];
            __nv_bfloat16 h = __float2bfloat16(v);
            g_Wcp[0][e] = h;
            g_Wcp[1][e] = __float2bfloat16(v - __bfloat162float(h));
        }
    }
}

// ---------------- kernel 2: single-block scan + re-zero cnt ----------------
__global__ void k_scanfill(const long long* __restrict__ ei64) {
    __shared__ int sums[1024];
    int t = threadIdx.x;
    const int CH = 10;
    int base = t*CH;
    int loc[CH];
    int s = 0;
    #pragma unroll
    for (int i = 0; i < CH; i++) {
        int idx = base + i;
        int v = (idx < NN) ? g_cnt[idx] : 0;
        loc[i] = s; s += v;
    }
    sums[t] = s;
    __syncthreads();
    for (int off = 1; off < 1024; off <<= 1) {
        int v = (t >= off) ? sums[t-off] : 0;
        __syncthreads();
        sums[t] += v;
        __syncthreads();
    }
    int prev = (t > 0) ? sums[t-1] : 0;
    #pragma unroll
    for (int i = 0; i < CH; i++) {
        int idx = base + i;
        if (idx < NN) {
            int v = prev + loc[i];
            g_rs[idx] = v;
            g_cur[idx] = v;
        }
    }
    if (t == 1023) g_rs[NN] = sums[1023];
    __syncthreads();
    for (int i = t; i < NN; i += 1024) g_cnt[i] = 0;   // for next replay
}

// ---------------- kernel 3: CSR fill (multi-block, atomic cursors) ------------
__global__ void k_fill(const long long* __restrict__ ei64,
                       const float* __restrict__ ew) {
    __shared__ int bad;
    if (threadIdx.x == 0) bad = 0;
    __syncthreads();
    long long v = ei64[threadIdx.x];
    if (v < 0 || v >= NN) atomicOr(&bad, 1);
    __syncthreads();
    int e = blockIdx.x*256 + threadIdx.x;
    int r, c;
    if (bad) {
        r = ((const int*)ei64)[e];
        c = ((const int*)ei64)[NE + e];
    } else {
        r = (int)ei64[e];
        c = (int)ei64[NE + e];
    }
    int pos = atomicAdd(&g_cur[r], 1);
    g_epack[pos] = make_float2(__int_as_float(c), ew[e]);
}

// ---------------- graph conv (CSR gather-reduce, feature-sliced, 2-edge) -------
#define CONV_FMA(acc, p, v) \
    acc.x = fmaf(p.y, v.x, acc.x); acc.y = fmaf(p.y, v.y, acc.y); \
    acc.z = fmaf(p.y, v.z, acc.z); acc.w = fmaf(p.y, v.w, acc.w);

template<int NV4>
__global__ __launch_bounds__(256) void k_conv(const float4* __restrict__ x,
                       const float4* __restrict__ base,
                       float4* __restrict__ out,
                       __nv_bfloat16* __restrict__ php,
                       __nv_bfloat16* __restrict__ plp,
                       float scale, int sub) {
    int n   = blockIdx.x;
    int idx = blockIdx.y*256 + threadIdx.x;
    const float4* xb = x + idx;
    float4 acc = make_float4(0.f, 0.f, 0.f, 0.f);
    int e0 = __ldg(&g_rs[n]);
    int e1 = __ldg(&g_rs[n+1]);
    int e = e0;
    for (; e + 2 <= e1; e += 2) {
        float2 p0 = __ldg(&g_epack[e]);
        float2 p1 = __ldg(&g_epack[e+1]);
        float4 v0 = __ldg(xb + __float_as_int(p0.x)*NV4);
        float4 v1 = __ldg(xb + __float_as_int(p1.x)*NV4);
        CONV_FMA(acc, p0, v0)
        CONV_FMA(acc, p1, v1)
    }
    if (e < e1) {
        float2 p0 = __ldg(&g_epack[e]);
        float4 v0 = __ldg(xb + __float_as_int(p0.x)*NV4);
        CONV_FMA(acc, p0, v0)
    }
    float4 r;
    if (sub) {
        float4 b = __ldg(&base[n*NV4 + idx]);
        r = make_float4(fmaf(scale, acc.x, -b.x), fmaf(scale, acc.y, -b.y),
                        fmaf(scale, acc.z, -b.z), fmaf(scale, acc.w, -b.w));
    } else {
        r = make_float4(scale*acc.x, scale*acc.y, scale*acc.z, scale*acc.w);
    }
    if (out) out[n*NV4 + idx] = r;     // plain store: re-gathered by next conv
    const int KW  = NV4/8;             // 128 or 64
    const int KW4 = KW/4;
    int b  = idx / KW4;
    int f4 = idx % KW4;
    size_t po = ((size_t)n*32 + b)*KW + f4*4;
    emit_planes(r, php, plp, po);
}

// ================= GEMM 1: gates (single-sync double buffer, ldmatrix) =========
// 12 sub-chunks of K=32. Stage buffer (40960 B): AHI 0, ALO 10240,
// BHI 20480, BLO 30720; pitch 80 B (32 bf16 + 16 pad). 2 stages = 81920 B.
extern __shared__ char dynsm[];

__device__ __forceinline__ void gates_stage(int c, int buf, int m0, int tid, u32 sb) {
    u32 base = sb + buf*40960;
    const __nv_bfloat16* Ah = &g_Xp[0][c >> 2][(c & 3)*32];
    const __nv_bfloat16* Al = &g_Xp[1][c >> 2][(c & 3)*32];
    int wcol = c*32;
    #pragma unroll
    for (int i = 0; i < 2; i++) {
        int f = tid + 256*i;           // 0..511
        int r = f >> 2, q = f & 3;
        u32 d = r*80 + q*16;
        size_t ao = (size_t)(m0 + r)*FF + q*8;
        int wo = r*384 + wcol + q*8;
        cpa16(base + d,         Ah + ao);
        cpa16(base + 10240 + d, Al + ao);
        cpa16(base + 20480 + d, &g_Wgp[0][wo]);
        cpa16(base + 30720 + d, &g_Wgp[1][wo]);
    }
}

__global__ __launch_bounds__(256, 2)
void k_gates_mma(const float* __restrict__ bg) {
    u32 sb = smem_u32(dynsm);
    int tid = threadIdx.x, wid = tid >> 5, lid = tid & 31;
    int g = lid >> 2, t = lid & 3;
    int m0 = blockIdx.x * 128;
    int rb = wid & 3, cb = wid >> 2;

    float acc[2][8][4];
    #pragma unroll
    for (int i = 0; i < 2; i++)
        #pragma unroll
        for (int j = 0; j < 8; j++)
            #pragma unroll
            for (int k = 0; k < 4; k++) acc[i][j][k] = 0.f;

    u32 a_row = (u32)(lid & 15);
    u32 a_kh  = (u32)(lid >> 4) * 16;
    u32 b_row = (u32)((lid & 7) + ((lid & 16) ? 8 : 0));
    u32 b_kh  = (lid & 8) ? 16u : 0u;

    gates_stage(0, 0, m0, tid, sb);
    CP_COMMIT();

    // single-sync pipeline:
    //  wait(stage c ready) -> sync(all finished compute c-1; safe to overwrite
    //  buf (c+1)&1) -> issue stage c+1 -> compute c (overlaps stage c+1)
    #pragma unroll 1
    for (int c = 0; c < 12; c++) {
        CP_WAIT0();
        __syncthreads();
        if (c < 11) {
            gates_stage(c+1, (c+1)&1, m0, tid, sb);
            CP_COMMIT();
        }
        u32 B0 = sb + (c&1)*40960;
        u32 sAHI = B0, sALO = B0 + 10240, sBHI = B0 + 20480, sBLO = B0 + 30720;
        #pragma unroll
        for (int ks = 0; ks < 2; ks++) {
            u32 kb = ks*32 + a_kh;
            u32 ah[8], al[8];
            ldsm4(ah[0], ah[1], ah[2], ah[3], sAHI + (rb*32 + a_row)*80 + kb);
            ldsm4(ah[4], ah[5], ah[6], ah[7], sAHI + (rb*32 + 16 + a_row)*80 + kb);
            ldsm4(al[0], al[1], al[2], al[3], sALO + (rb*32 + a_row)*80 + kb);
            ldsm4(al[4], al[5], al[6], al[7], sALO + (rb*32 + 16 + a_row)*80 + kb);
            u32 kbb = ks*32 + b_kh;
            #pragma unroll
            for (int p = 0; p < 4; p++) {
                u32 brow = (cb*64 + p*16 + b_row)*80 + kbb;
                u32 bh0, bh1, bh2, bh3, bl0, bl1, bl2, bl3;
                ldsm4(bh0, bh1, bh2, bh3, sBHI + brow);
                ldsm4(bl0, bl1, bl2, bl3, sBLO + brow);
                mma_bf16(acc[0][2*p],   ah[0], ah[1], ah[2], ah[3], bh0, bh1);
                mma_bf16(acc[1][2*p],   ah[4], ah[5], ah[6], ah[7], bh0, bh1);
                mma_bf16(acc[0][2*p+1], ah[0], ah[1], ah[2], ah[3], bh2, bh3);
                mma_bf16(acc[1][2*p+1], ah[4], ah[5], ah[6], ah[7], bh2, bh3);
                mma_bf16(acc[0][2*p],   ah[0], ah[1], ah[2], ah[3], bl0, bl1);
                mma_bf16(acc[1][2*p],   ah[4], ah[5], ah[6], ah[7], bl0, bl1);
                mma_bf16(acc[0][2*p+1], ah[0], ah[1], ah[2], ah[3], bl2, bl3);
                mma_bf16(acc[1][2*p+1], ah[4], ah[5], ah[6], ah[7], bl2, bl3);
                mma_bf16(acc[0][2*p],   al[0], al[1], al[2], al[3], bh0, bh1);
                mma_bf16(acc[1][2*p],   al[4], al[5], al[6], al[7], bh0, bh1);
                mma_bf16(acc[0][2*p+1], al[0], al[1], al[2], al[3], bh2, bh3);
                mma_bf16(acc[1][2*p+1], al[4], al[5], al[6], al[7], bh2, bh3);
            }
        }
    }
    __syncthreads();

    // epilogue: fragments -> smem D tile -> coalesced sigmoid writes
    float* D = (float*)dynsm;          // 128 x 132 fp32
    #pragma unroll
    for (int ma = 0; ma < 2; ma++) {
        int row = rb*32 + ma*16 + g;
        #pragma unroll
        for (int na = 0; na < 8; na++) {
            int col = cb*64 + na*8 + 2*t;
            *(float2*)&D[row*132 + col]     = make_float2(acc[ma][na][0], acc[ma][na][1]);
            *(float2*)&D[(row+8)*132 + col] = make_float2(acc[ma][na][2], acc[ma][na][3]);
        }
    }
    __syncthreads();
    #pragma unroll
    for (int i = 0; i < 16; i++) {
        int f = tid + 256*i;           // 0..4095
        int r = f >> 5, c4 = f & 31;
        int col = c4*4;
        size_t m = (size_t)(m0 + r);
        float4 v = *(const float4*)&D[r*132 + col];
        float4 b4 = *(const float4*)&bg[col];
        float s0 = fast_sigmoid(v.x + b4.x);
        float s1 = fast_sigmoid(v.y + b4.y);
        float s2 = fast_sigmoid(v.z + b4.z);
        float s3 = fast_sigmoid(v.w + b4.w);
        if (col < 64) {
            *(float4*)&g_Z[m*DOUT + col] = make_float4(s0, s1, s2, s3);
        } else {
            float4 hv = *(const float4*)&g_X[0][m*FF + col];
            float4 rh = make_float4(s0*hv.x, s1*hv.y, s2*hv.z, s3*hv.w);
            size_t po = m*DOUT + (col - 64);
            *(float4*)&g_H[0][po] = rh;
            emit_planes(rh, g_Hp[0][0], g_Hp[1][0], po);
        }
    }
}

// ================= GEMM 2: candidate (single-sync double buffer) ===============
// Stage buffer (30720 B): AHI 0, ALO 10240, BHI 20480 (64x80), BLO 25600.
__device__ __forceinline__ void cand_stage(int c, int buf, int m0, int tid, u32 sb) {
    u32 base = sb + buf*30720;
    int c2 = c >> 1;
    const __nv_bfloat16 *Ah, *Al;
    int rs;
    if ((c2 & 1) == 0) {
        Ah = &g_Xp[0][c2 >> 1][(c & 1)*32];
        Al = &g_Xp[1][c2 >> 1][(c & 1)*32];
        rs = FF;
    } else {
        Ah = &g_Hp[0][c2 >> 1][(c & 1)*32];
        Al = &g_Hp[1][c2 >> 1][(c & 1)*32];
        rs = DOUT;
    }
    int wcol = c*32;
    #pragma unroll
    for (int i = 0; i < 2; i++) {
        int f = tid + 256*i;
        int r = f >> 2, q = f & 3;
        u32 d = r*80 + q*16;
        size_t ao = (size_t)(m0 + r)*rs + q*8;
        cpa16(base + d,         Ah + ao);
        cpa16(base + 10240 + d, Al + ao);
    }
    {
        int f = tid;
        int r = f >> 2, q = f & 3;
        u32 d = r*80 + q*16;
        int wo = r*384 + wcol + q*8;
        cpa16(base + 20480 + d, &g_Wcp[0][wo]);
        cpa16(base + 25600 + d, &g_Wcp[1][wo]);
    }
}

__global__ __launch_bounds__(256, 2)
void k_cand_mma(const float* __restrict__ bc, float* __restrict__ out) {
    u32 sb = smem_u32(dynsm);
    int tid = threadIdx.x, wid = tid >> 5, lid = tid & 31;
    int g = lid >> 2, t = lid & 3;
    int m0 = blockIdx.x * 128;
    int rb = wid & 3, cb = wid >> 2;

    float acc[2][4][4];
    #pragma unroll
    for (int i = 0; i < 2; i++)
        #pragma unroll
        for (int j = 0; j < 4; j++)
            #pragma unroll
            for (int k = 0; k < 4; k++) acc[i][j][k] = 0.f;

    u32 a_row = (u32)(lid & 15);
    u32 a_kh  = (u32)(lid >> 4) * 16;
    u32 b_row = (u32)((lid & 7) + ((lid & 16) ? 8 : 0));
    u32 b_kh  = (lid & 8) ? 16u : 0u;

    cand_stage(0, 0, m0, tid, sb);
    CP_COMMIT();

    #pragma unroll 1
    for (int c = 0; c < 12; c++) {
        CP_WAIT0();
        __syncthreads();
        if (c < 11) {
            cand_stage(c+1, (c+1)&1, m0, tid, sb);
            CP_COMMIT();
        }
        u32 B0 = sb + (c&1)*30720;
        u32 sAHI = B0, sALO = B0 + 10240, sBHI = B0 + 20480, sBLO = B0 + 25600;
        #pragma unroll
        for (int ks = 0; ks < 2; ks++) {
            u32 kb = ks*32 + a_kh;
            u32 ah[8], al[8];
            ldsm4(ah[0], ah[1], ah[2], ah[3], sAHI + (rb*32 + a_row)*80 + kb);
            ldsm4(ah[4], ah[5], ah[6], ah[7], sAHI + (rb*32 + 16 + a_row)*80 + kb);
            ldsm4(al[0], al[1], al[2], al[3], sALO + (rb*32 + a_row)*80 + kb);
            ldsm4(al[4], al[5], al[6], al[7], sALO + (rb*32 + 16 + a_row)*80 + kb);
            u32 kbb = ks*32 + b_kh;
            #pragma unroll
            for (int p = 0; p < 2; p++) {
                u32 brow = (cb*32 + p*16 + b_row)*80 + kbb;
                u32 bh0, bh1, bh2, bh3, bl0, bl1, bl2, bl3;
                ldsm4(bh0, bh1, bh2, bh3, sBHI + brow);
                ldsm4(bl0, bl1, bl2, bl3, sBLO + brow);
                mma_bf16(acc[0][2*p],   ah[0], ah[1], ah[2], ah[3], bh0, bh1);
                mma_bf16(acc[1][2*p],   ah[4], ah[5], ah[6], ah[7], bh0, bh1);
                mma_bf16(acc[0][2*p+1], ah[0], ah[1], ah[2], ah[3], bh2, bh3);
                mma_bf16(acc[1][2*p+1], ah[4], ah[5], ah[6], ah[7], bh2, bh3);
                mma_bf16(acc[0][2*p],   ah[0], ah[1], ah[2], ah[3], bl0, bl1);
                mma_bf16(acc[1][2*p],   ah[4], ah[5], ah[6], ah[7], bl0, bl1);
                mma_bf16(acc[0][2*p+1], ah[0], ah[1], ah[2], ah[3], bl2, bl3);
                mma_bf16(acc[1][2*p+1], ah[4], ah[5], ah[6], ah[7], bl2, bl3);
                mma_bf16(acc[0][2*p],   al[0], al[1], al[2], al[3], bh0, bh1);
                mma_bf16(acc[1][2*p],   al[4], al[5], al[6], al[7], bh0, bh1);
                mma_bf16(acc[0][2*p+1], al[0], al[1], al[2], al[3], bh2, bh3);
                mma_bf16(acc[1][2*p+1], al[4], al[5], al[6], al[7], bh2, bh3);
            }
        }
    }
    __syncthreads();

    // epilogue: fragments -> smem -> coalesced tanh/combine writes
    float* D = (float*)dynsm;          // 128 x 68 fp32
    #pragma unroll
    for (int ma = 0; ma < 2; ma++) {
        int row = rb*32 + ma*16 + g;
        #pragma unroll
        for (int na = 0; na < 4; na++) {
            int col = cb*32 + na*8 + 2*t;
            *(float2*)&D[row*68 + col]     = make_float2(acc[ma][na][0], acc[ma][na][1]);
            *(float2*)&D[(row+8)*68 + col] = make_float2(acc[ma][na][2], acc[ma][na][3]);
        }
    }
    __syncthreads();
    #pragma unroll
    for (int i = 0; i < 8; i++) {
        int f = tid + 256*i;           // 0..2047
        int r = f >> 4, c4 = f & 15;
        int col = c4*4;
        size_t m = (size_t)(m0 + r);
        int n = (int)(m >> 5);
        int b = (int)(m & 31);
        float4 v = *(const float4*)&D[r*68 + col];
        float4 b4 = *(const float4*)&bc[col];
        float cd0 = fast_tanh(v.x + b4.x);
        float cd1 = fast_tanh(v.y + b4.y);
        float cd2 = fast_tanh(v.z + b4.z);
        float cd3 = fast_tanh(v.w + b4.w);
        float4 z4 = *(const float4*)&g_Z[m*DOUT + col];
        float4 h4 = *(const float4*)&g_X[0][m*FF + 64 + col];
        float4 r4 = make_float4((1.f - z4.x)*h4.x + z4.x*cd0,
                                (1.f - z4.y)*h4.y + z4.y*cd1,
                                (1.f - z4.z)*h4.z + z4.z*cd2,
                                (1.f - z4.w)*h4.w + z4.w*cd3);
        *(float4*)&out[(size_t)b*(NN*DOUT) + (size_t)n*DOUT + col] = r4;
    }
}

// ---------------- launch ----------------
extern "C" void kernel_launch(void* const* d_in, const int* in_sizes, int n_in,
                              void* d_out, int out_size) {
    const float* inp = nullptr;
    const float* hx  = nullptr;
    const void*  ei  = nullptr;
    const float* ew  = nullptr;
    const float* Wg  = nullptr;
    const float* Wc  = nullptr;
    const float* bg  = nullptr;
    const float* bc  = nullptr;
    for (int i = 0; i < n_in; i++) {
        switch (in_sizes[i]) {
            case 20480000: if (!inp) inp = (const float*)d_in[i];
                           else      hx  = (const float*)d_in[i]; break;
            case 320000:   ei = d_in[i];                 break;
            case 160000:   ew = (const float*)d_in[i];   break;
            case 49152:    Wg = (const float*)d_in[i];   break;
            case 24576:    Wc = (const float*)d_in[i];   break;
            case 128:      bg = (const float*)d_in[i];   break;
            case 64:       bc = (const float*)d_in[i];   break;
            default: break;
        }
    }
    float* out = (float*)d_out;

    void *pX, *pH, *pXp, *pHp;
    cudaGetSymbolAddress(&pX, g_X);
    cudaGetSymbolAddress(&pH, g_H);
    cudaGetSymbolAddress(&pXp, g_Xp);
    cudaGetSymbolAddress(&pHp, g_Hp);
    float* X = (float*)pX;
    float* H = (float*)pH;
    __nv_bfloat16* Xp = (__nv_bfloat16*)pXp;   // [hi/lo][s][XPS]
    __nv_bfloat16* Hp = (__nv_bfloat16*)pHp;

    cudaFuncSetAttribute(k_gates_mma, cudaFuncAttributeMaxDynamicSharedMemorySize, 81920);
    cudaFuncSetAttribute(k_cand_mma,  cudaFuncAttributeMaxDynamicSharedMemorySize, 61440);

    // 1-3: CSR + X0 (+ planes) + weight planes
    k_histbuild<<<HIST_BLKS + NN + WPL_BLKS, 256>>>((const long long*)ei, inp, hx, Wg, Wc);
    k_scanfill<<<1, 1024>>>((const long long*)ei);
    k_fill<<<HIST_BLKS, 256>>>((const long long*)ei, ew);

    // 4-5: first diffusion (X1 fp32+planes; X2 planes only)
    dim3 gf(NN, 4);
    k_conv<V4F><<<gf, 256>>>((const float4*)X,          nullptr,
                             (float4*)(X + XPS),
                             Xp + 1*XPS, Xp + (3+1)*XPS, 1.f, 0);
    k_conv<V4F><<<gf, 256>>>((const float4*)(X + XPS),  (const float4*)X,
                             nullptr,
                             Xp + 2*XPS, Xp + (3+2)*XPS, 2.f, 1);

    // 6: gates GEMM -> z, RH (fp32 + planes)
    k_gates_mma<<<MM/128, 256, 81920>>>(bg);

    // 7-8: second diffusion on RH (D1 fp32+planes; D2 planes only)
    dim3 gh(NN, 2);
    k_conv<V4H><<<gh, 256>>>((const float4*)H,          nullptr,
                             (float4*)(H + HPS),
                             Hp + 1*HPS, Hp + (3+1)*HPS, 1.f, 0);
    k_conv<V4H><<<gh, 256>>>((const float4*)(H + HPS),  (const float4*)H,
                             nullptr,
                             Hp + 2*HPS, Hp + (3+2)*HPS, 2.f, 1);

    // 9: candidate GEMM + combine + transpose
    k_cand_mma<<<MM/128, 256, 61440>>>(bc, out);
}

// round 15
// speedup vs baseline: 1.0096x; 1.0096x over previous
#include <cuda_runtime.h>
#include <cuda_bf16.h>
#include <math.h>
#include <stdint.h>

// Problem constants (fixed by the reference)
#define NN   10000            // nodes
#define NB   32               // batch
#define DIN  64
#define DOUT 64
#define FF   128              // DIN + DOUT
#define NE   160000           // edges
#define MM   (NN*NB)          // 320000 rows (node-major: m = n*32 + b)
#define V4F  1024             // float4 per node (full width)
#define V4H  512              // float4 per node (half width)
#define XPS  ((size_t)MM*FF)   // X plane elems per stage
#define HPS  ((size_t)MM*DOUT) // H plane elems per stage

typedef unsigned long long u64;
typedef unsigned int u32;

// ---------------- scratch (device globals; allocation-free) ----------------
__device__ __align__(16) float g_X[2][XPS];    // X0, X1 fp32 (conv operands)
__device__ __align__(16) float g_H[2][HPS];    // RH, D1 fp32 (conv operands)
__device__ __align__(16) float g_Z[HPS];       // update gate z
__device__ __align__(16) __nv_bfloat16 g_Xp[2][3][XPS];   // [hi/lo][stage]
__device__ __align__(16) __nv_bfloat16 g_Hp[2][3][HPS];
__device__ __align__(16) __nv_bfloat16 g_Wgp[2][128*384];
__device__ __align__(16) __nv_bfloat16 g_Wcp[2][64*384];
__device__ int    g_cnt[NN];
__device__ int    g_rs [NN+1];
__device__ int    g_cur[NN];
__device__ __align__(8) float2 g_epack[NE];   // {col as int bits, weight}

// ---------------- bf16 hi/lo split helpers ----------------
__device__ __forceinline__ unsigned packhi2(float a, float b, float& ra, float& rb) {
    __nv_bfloat16 ha = __float2bfloat16(a), hb = __float2bfloat16(b);
    ra = a - __bfloat162float(ha);
    rb = b - __bfloat162float(hb);
    __nv_bfloat162 t = __halves2bfloat162(ha, hb);
    return *reinterpret_cast<unsigned*>(&t);
}
__device__ __forceinline__ unsigned packlo2(float a, float b) {
    __nv_bfloat162 t = __floats2bfloat162_rn(a, b);
    return *reinterpret_cast<unsigned*>(&t);
}
__device__ __forceinline__ void emit_planes(float4 v, __nv_bfloat16* hp,
                                            __nv_bfloat16* lp, size_t po) {
    float r0, r1, r2, r3;
    unsigned h0 = packhi2(v.x, v.y, r0, r1);
    unsigned h1 = packhi2(v.z, v.w, r2, r3);
    *(uint2*)&hp[po] = make_uint2(h0, h1);
    *(uint2*)&lp[po] = make_uint2(packlo2(r0, r1), packlo2(r2, r3));
}

__device__ __forceinline__ u32 smem_u32(const void* p) {
    u32 a;
    asm("{ .reg .u64 t; cvta.to.shared.u64 t, %1; cvt.u32.u64 %0, t; }"
        : "=r"(a) : "l"(p));
    return a;
}
__device__ __forceinline__ void cpa16(u32 dst, const void* src) {
    asm volatile("cp.async.ca.shared.global [%0], [%1], 16;"
                 :: "r"(dst), "l"(src) : "memory");
}
#define CP_COMMIT() asm volatile("cp.async.commit_group;" ::: "memory")
#define CP_WAIT1()  asm volatile("cp.async.wait_group 1;"  ::: "memory")
#define CP_WAIT0()  asm volatile("cp.async.wait_group 0;"  ::: "memory")

// ldmatrix x4: four 8x8 bf16 fragments in one instruction (sm_75+ family PTX)
__device__ __forceinline__ void ldsm4(u32& r0, u32& r1, u32& r2, u32& r3, u32 addr) {
    asm volatile("ldmatrix.sync.aligned.m8n8.x4.shared.b16 {%0,%1,%2,%3}, [%4];"
        : "=r"(r0), "=r"(r1), "=r"(r2), "=r"(r3) : "r"(addr));
}

// mma.sync m16n8k16 row.col f32.bf16.bf16.f32 (family PTX, sm_80+)
__device__ __forceinline__ void mma_bf16(float* c,
        u32 a0, u32 a1, u32 a2, u32 a3, u32 b0, u32 b1) {
    asm volatile("mma.sync.aligned.m16n8k16.row.col.f32.bf16.bf16.f32 "
        "{%0,%1,%2,%3}, {%4,%5,%6,%7}, {%8,%9}, {%0,%1,%2,%3};"
        : "+f"(c[0]), "+f"(c[1]), "+f"(c[2]), "+f"(c[3])
        : "r"(a0), "r"(a1), "r"(a2), "r"(a3), "r"(b0), "r"(b1));
}

// ---------------- fast activations ----------------
__device__ __forceinline__ float fast_sigmoid(float g) {
    return __fdividef(1.f, 1.f + __expf(-g));
}
__device__ __forceinline__ float fast_tanh(float x) {
    float t = __expf(-2.f * fabsf(x));
    float r = __fdividef(1.f - t, 1.f + t);
    return copysignf(r, x);
}

// ---------------- kernel 1: histogram / build X0+planes / weight planes --------
#define HIST_BLKS (NE/256)     // 625
#define WPL_BLKS  64
__global__ void k_histbuild(const long long* __restrict__ ei64,
                            const float* __restrict__ in,
                            const float* __restrict__ hx,
                            const float* __restrict__ Wg,
                            const float* __restrict__ Wc) {
    if (blockIdx.x < HIST_BLKS) {
        __shared__ int bad;
        if (threadIdx.x == 0) bad = 0;
        __syncthreads();
        long long v = ei64[threadIdx.x];
        if (v < 0 || v >= NN) atomicOr(&bad, 1);
        __syncthreads();
        int e = blockIdx.x*256 + threadIdx.x;
        int r;
        if (bad) r = ((const int*)ei64)[e];
        else     r = (int)ei64[e];
        atomicAdd(&g_cnt[r], 1);
    } else if (blockIdx.x < HIST_BLKS + NN) {
        int n = blockIdx.x - HIST_BLKS;
        const float4* in4 = (const float4*)in;
        const float4* hx4 = (const float4*)hx;
        for (int i = threadIdx.x; i < 512; i += 256) {
            int b = i >> 4, f4 = i & 15;
            size_t m = (size_t)n*32 + b;
            size_t po = m*FF + f4*4;
            float4 v = __ldg(&in4[((size_t)b*NN + n)*16 + f4]);
            *(float4*)&g_X[0][po] = v;
            emit_planes(v, g_Xp[0][0], g_Xp[1][0], po);
            float4 w = __ldg(&hx4[((size_t)b*NN + n)*16 + f4]);
            *(float4*)&g_X[0][po + 64] = w;
            emit_planes(w, g_Xp[0][0], g_Xp[1][0], po + 64);
        }
    } else {
        int j = blockIdx.x - (HIST_BLKS + NN);
        for (int e = j*768 + threadIdx.x; e < (j+1)*768; e += 256) {
            float v = Wg[e];
            __nv_bfloat16 h = __float2bfloat16(v);
            g_Wgp[0][e] = h;
            g_Wgp[1][e] = __float2bfloat16(v - __bfloat162float(h));
        }
        for (int e = j*384 + threadIdx.x; e < (j+1)*384; e += 256) {
            float v = Wc[e];
            __nv_bfloat16 h = __float2bfloat16(v);
            g_Wcp[0][e] = h;
            g_Wcp[1][e] = __float2bfloat16(v - __bfloat162float(h));
        }
    }
}

// ---------------- kernel 2: single-block scan + re-zero cnt ----------------
__global__ void k_scanfill(const long long* __restrict__ ei64) {
    __shared__ int sums[1024];
    int t = threadIdx.x;
    const int CH = 10;
    int base = t*CH;
    int loc[CH];
    int s = 0;
    #pragma unroll
    for (int i = 0; i < CH; i++) {
        int idx = base + i;
        int v = (idx < NN) ? g_cnt[idx] : 0;
        loc[i] = s; s += v;
    }
    sums[t] = s;
    __syncthreads();
    for (int off = 1; off < 1024; off <<= 1) {
        int v = (t >= off) ? sums[t-off] : 0;
        __syncthreads();
        sums[t] += v;
        __syncthreads();
    }
    int prev = (t > 0) ? sums[t-1] : 0;
    #pragma unroll
    for (int i = 0; i < CH; i++) {
        int idx = base + i;
        if (idx < NN) {
            int v = prev + loc[i];
            g_rs[idx] = v;
            g_cur[idx] = v;
        }
    }
    if (t == 1023) g_rs[NN] = sums[1023];
    __syncthreads();
    for (int i = t; i < NN; i += 1024) g_cnt[i] = 0;   // for next replay
}

// ---------------- kernel 3: CSR fill (multi-block, atomic cursors) ------------
__global__ void k_fill(const long long* __restrict__ ei64,
                       const float* __restrict__ ew) {
    __shared__ int bad;
    if (threadIdx.x == 0) bad = 0;
    __syncthreads();
    long long v = ei64[threadIdx.x];
    if (v < 0 || v >= NN) atomicOr(&bad, 1);
    __syncthreads();
    int e = blockIdx.x*256 + threadIdx.x;
    int r, c;
    if (bad) {
        r = ((const int*)ei64)[e];
        c = ((const int*)ei64)[NE + e];
    } else {
        r = (int)ei64[e];
        c = (int)ei64[NE + e];
    }
    int pos = atomicAdd(&g_cur[r], 1);
    g_epack[pos] = make_float2(__int_as_float(c), ew[e]);
}

// ---------------- graph conv (CSR gather-reduce, feature-sliced, 2-edge) -------
#define CONV_FMA(acc, p, v) \
    acc.x = fmaf(p.y, v.x, acc.x); acc.y = fmaf(p.y, v.y, acc.y); \
    acc.z = fmaf(p.y, v.z, acc.z); acc.w = fmaf(p.y, v.w, acc.w);

template<int NV4>
__global__ __launch_bounds__(256) void k_conv(const float4* __restrict__ x,
                       const float4* __restrict__ base,
                       float4* __restrict__ out,
                       __nv_bfloat16* __restrict__ php,
                       __nv_bfloat16* __restrict__ plp,
                       float scale, int sub) {
    int n   = blockIdx.x;
    int idx = blockIdx.y*256 + threadIdx.x;
    const float4* xb = x + idx;
    float4 acc = make_float4(0.f, 0.f, 0.f, 0.f);
    int e0 = __ldg(&g_rs[n]);
    int e1 = __ldg(&g_rs[n+1]);
    int e = e0;
    for (; e + 2 <= e1; e += 2) {
        float2 p0 = __ldg(&g_epack[e]);
        float2 p1 = __ldg(&g_epack[e+1]);
        float4 v0 = __ldg(xb + __float_as_int(p0.x)*NV4);
        float4 v1 = __ldg(xb + __float_as_int(p1.x)*NV4);
        CONV_FMA(acc, p0, v0)
        CONV_FMA(acc, p1, v1)
    }
    if (e < e1) {
        float2 p0 = __ldg(&g_epack[e]);
        float4 v0 = __ldg(xb + __float_as_int(p0.x)*NV4);
        CONV_FMA(acc, p0, v0)
    }
    float4 r;
    if (sub) {
        float4 b = __ldg(&base[n*NV4 + idx]);
        r = make_float4(fmaf(scale, acc.x, -b.x), fmaf(scale, acc.y, -b.y),
                        fmaf(scale, acc.z, -b.z), fmaf(scale, acc.w, -b.w));
    } else {
        r = make_float4(scale*acc.x, scale*acc.y, scale*acc.z, scale*acc.w);
    }
    if (out) __stcs(&out[n*NV4 + idx], r);
    const int KW  = NV4/8;         // 128 or 64
    const int KW4 = KW/4;
    int b  = idx / KW4;
    int f4 = idx % KW4;
    size_t po = ((size_t)n*32 + b)*KW + f4*4;
    emit_planes(r, php, plp, po);
}

// ================= GEMM 1: gates (double-buffered k32, ldmatrix) ===============
// 12 sub-chunks of K=32. Stage buffer (40960 B): AHI 0, ALO 10240,
// BHI 20480, BLO 30720; pitch 80 B (32 bf16 + 16 pad). 2 stages = 81920 B.
extern __shared__ char dynsm[];

__device__ __forceinline__ void gates_stage(int c, int buf, int m0, int tid, u32 sb) {
    u32 base = sb + buf*40960;
    const __nv_bfloat16* Ah = &g_Xp[0][c >> 2][(c & 3)*32];
    const __nv_bfloat16* Al = &g_Xp[1][c >> 2][(c & 3)*32];
    int wcol = c*32;
    #pragma unroll
    for (int i = 0; i < 2; i++) {
        int f = tid + 256*i;           // 0..511
        int r = f >> 2, q = f & 3;
        u32 d = r*80 + q*16;
        size_t ao = (size_t)(m0 + r)*FF + q*8;
        int wo = r*384 + wcol + q*8;
        cpa16(base + d,         Ah + ao);
        cpa16(base + 10240 + d, Al + ao);
        cpa16(base + 20480 + d, &g_Wgp[0][wo]);
        cpa16(base + 30720 + d, &g_Wgp[1][wo]);
    }
}

__global__ __launch_bounds__(256, 2)
void k_gates_mma(const float* __restrict__ bg) {
    u32 sb = smem_u32(dynsm);
    int tid = threadIdx.x, wid = tid >> 5, lid = tid & 31;
    int g = lid >> 2, t = lid & 3;
    int m0 = blockIdx.x * 128;
    int rb = wid & 3, cb = wid >> 2;

    float acc[2][8][4];
    #pragma unroll
    for (int i = 0; i < 2; i++)
        #pragma unroll
        for (int j = 0; j < 8; j++)
            #pragma unroll
            for (int k = 0; k < 4; k++) acc[i][j][k] = 0.f;

    u32 a_row = (u32)(lid & 15);
    u32 a_kh  = (u32)(lid >> 4) * 16;
    u32 b_row = (u32)((lid & 7) + ((lid & 16) ? 8 : 0));
    u32 b_kh  = (lid & 8) ? 16u : 0u;

    gates_stage(0, 0, m0, tid, sb);
    CP_COMMIT();

    #pragma unroll 1
    for (int c = 0; c < 12; c++) {
        if (c < 11) {
            gates_stage(c+1, (c+1)&1, m0, tid, sb);
            CP_COMMIT();
            CP_WAIT1();
        } else {
            CP_WAIT0();
        }
        __syncthreads();
        u32 B0 = sb + (c&1)*40960;
        u32 sAHI = B0, sALO = B0 + 10240, sBHI = B0 + 20480, sBLO = B0 + 30720;
        #pragma unroll
        for (int ks = 0; ks < 2; ks++) {
            u32 kb = ks*32 + a_kh;
            u32 ah[8], al[8];
            ldsm4(ah[0], ah[1], ah[2], ah[3], sAHI + (rb*32 + a_row)*80 + kb);
            ldsm4(ah[4], ah[5], ah[6], ah[7], sAHI + (rb*32 + 16 + a_row)*80 + kb);
            ldsm4(al[0], al[1], al[2], al[3], sALO + (rb*32 + a_row)*80 + kb);
            ldsm4(al[4], al[5], al[6], al[7], sALO + (rb*32 + 16 + a_row)*80 + kb);
            u32 kbb = ks*32 + b_kh;
            #pragma unroll
            for (int p = 0; p < 4; p++) {
                u32 brow = (cb*64 + p*16 + b_row)*80 + kbb;
                u32 bh0, bh1, bh2, bh3, bl0, bl1, bl2, bl3;
                ldsm4(bh0, bh1, bh2, bh3, sBHI + brow);
                ldsm4(bl0, bl1, bl2, bl3, sBLO + brow);
                mma_bf16(acc[0][2*p],   ah[0], ah[1], ah[2], ah[3], bh0, bh1);
                mma_bf16(acc[1][2*p],   ah[4], ah[5], ah[6], ah[7], bh0, bh1);
                mma_bf16(acc[0][2*p+1], ah[0], ah[1], ah[2], ah[3], bh2, bh3);
                mma_bf16(acc[1][2*p+1], ah[4], ah[5], ah[6], ah[7], bh2, bh3);
                mma_bf16(acc[0][2*p],   ah[0], ah[1], ah[2], ah[3], bl0, bl1);
                mma_bf16(acc[1][2*p],   ah[4], ah[5], ah[6], ah[7], bl0, bl1);
                mma_bf16(acc[0][2*p+1], ah[0], ah[1], ah[2], ah[3], bl2, bl3);
                mma_bf16(acc[1][2*p+1], ah[4], ah[5], ah[6], ah[7], bl2, bl3);
                mma_bf16(acc[0][2*p],   al[0], al[1], al[2], al[3], bh0, bh1);
                mma_bf16(acc[1][2*p],   al[4], al[5], al[6], al[7], bh0, bh1);
                mma_bf16(acc[0][2*p+1], al[0], al[1], al[2], al[3], bh2, bh3);
                mma_bf16(acc[1][2*p+1], al[4], al[5], al[6], al[7], bh2, bh3);
            }
        }
        __syncthreads();
    }

    // epilogue: fragments -> smem D tile -> coalesced sigmoid writes
    float* D = (float*)dynsm;          // 128 x 132 fp32
    #pragma unroll
    for (int ma = 0; ma < 2; ma++) {
        int row = rb*32 + ma*16 + g;
        #pragma unroll
        for (int na = 0; na < 8; na++) {
            int col = cb*64 + na*8 + 2*t;
            *(float2*)&D[row*132 + col]     = make_float2(acc[ma][na][0], acc[ma][na][1]);
            *(float2*)&D[(row+8)*132 + col] = make_float2(acc[ma][na][2], acc[ma][na][3]);
        }
    }
    __syncthreads();
    #pragma unroll
    for (int i = 0; i < 16; i++) {
        int f = tid + 256*i;           // 0..4095
        int r = f >> 5, c4 = f & 31;
        int col = c4*4;
        size_t m = (size_t)(m0 + r);
        float4 v = *(const float4*)&D[r*132 + col];
        float4 b4 = *(const float4*)&bg[col];
        float s0 = fast_sigmoid(v.x + b4.x);
        float s1 = fast_sigmoid(v.y + b4.y);
        float s2 = fast_sigmoid(v.z + b4.z);
        float s3 = fast_sigmoid(v.w + b4.w);
        if (col < 64) {
            *(float4*)&g_Z[m*DOUT + col] = make_float4(s0, s1, s2, s3);
        } else {
            float4 hv = *(const float4*)&g_X[0][m*FF + col];
            float4 rh = make_float4(s0*hv.x, s1*hv.y, s2*hv.z, s3*hv.w);
            size_t po = m*DOUT + (col - 64);
            *(float4*)&g_H[0][po] = rh;
            emit_planes(rh, g_Hp[0][0], g_Hp[1][0], po);
        }
    }
}

// ================= GEMM 2: candidate (double-buffered k32, ldmatrix) ===========
// Stage buffer (30720 B): AHI 0, ALO 10240, BHI 20480 (64x80), BLO 25600.
// occ 3 blocks/SM: smem 3x61440=184K <= 228K; launch_bounds caps regs at 85.
__device__ __forceinline__ void cand_stage(int c, int buf, int m0, int tid, u32 sb) {
    u32 base = sb + buf*30720;
    int c2 = c >> 1;
    const __nv_bfloat16 *Ah, *Al;
    int rs;
    if ((c2 & 1) == 0) {
        Ah = &g_Xp[0][c2 >> 1][(c & 1)*32];
        Al = &g_Xp[1][c2 >> 1][(c & 1)*32];
        rs = FF;
    } else {
        Ah = &g_Hp[0][c2 >> 1][(c & 1)*32];
        Al = &g_Hp[1][c2 >> 1][(c & 1)*32];
        rs = DOUT;
    }
    int wcol = c*32;
    #pragma unroll
    for (int i = 0; i < 2; i++) {
        int f = tid + 256*i;
        int r = f >> 2, q = f & 3;
        u32 d = r*80 + q*16;
        size_t ao = (size_t)(m0 + r)*rs + q*8;
        cpa16(base + d,         Ah + ao);
        cpa16(base + 10240 + d, Al + ao);
    }
    {
        int f = tid;
        int r = f >> 2, q = f & 3;
        u32 d = r*80 + q*16;
        int wo = r*384 + wcol + q*8;
        cpa16(base + 20480 + d, &g_Wcp[0][wo]);
        cpa16(base + 25600 + d, &g_Wcp[1][wo]);
    }
}

__global__ __launch_bounds__(256, 3)
void k_cand_mma(const float* __restrict__ bc, float* __restrict__ out) {
    u32 sb = smem_u32(dynsm);
    int tid = threadIdx.x, wid = tid >> 5, lid = tid & 31;
    int g = lid >> 2, t = lid & 3;
    int m0 = blockIdx.x * 128;
    int rb = wid & 3, cb = wid >> 2;

    float acc[2][4][4];
    #pragma unroll
    for (int i = 0; i < 2; i++)
        #pragma unroll
        for (int j = 0; j < 4; j++)
            #pragma unroll
            for (int k = 0; k < 4; k++) acc[i][j][k] = 0.f;

    u32 a_row = (u32)(lid & 15);
    u32 a_kh  = (u32)(lid >> 4) * 16;
    u32 b_row = (u32)((lid & 7) + ((lid & 16) ? 8 : 0));
    u32 b_kh  = (lid & 8) ? 16u : 0u;

    cand_stage(0, 0, m0, tid, sb);
    CP_COMMIT();

    #pragma unroll 1
    for (int c = 0; c < 12; c++) {
        if (c < 11) {
            cand_stage(c+1, (c+1)&1, m0, tid, sb);
            CP_COMMIT();
            CP_WAIT1();
        } else {
            CP_WAIT0();
        }
        __syncthreads();
        u32 B0 = sb + (c&1)*30720;
        u32 sAHI = B0, sALO = B0 + 10240, sBHI = B0 + 20480, sBLO = B0 + 25600;
        #pragma unroll
        for (int ks = 0; ks < 2; ks++) {
            u32 kb = ks*32 + a_kh;
            u32 ah[8], al[8];
            ldsm4(ah[0], ah[1], ah[2], ah[3], sAHI + (rb*32 + a_row)*80 + kb);
            ldsm4(ah[4], ah[5], ah[6], ah[7], sAHI + (rb*32 + 16 + a_row)*80 + kb);
            ldsm4(al[0], al[1], al[2], al[3], sALO + (rb*32 + a_row)*80 + kb);
            ldsm4(al[4], al[5], al[6], al[7], sALO + (rb*32 + 16 + a_row)*80 + kb);
            u32 kbb = ks*32 + b_kh;
            #pragma unroll
            for (int p = 0; p < 2; p++) {
                u32 brow = (cb*32 + p*16 + b_row)*80 + kbb;
                u32 bh0, bh1, bh2, bh3, bl0, bl1, bl2, bl3;
                ldsm4(bh0, bh1, bh2, bh3, sBHI + brow);
                ldsm4(bl0, bl1, bl2, bl3, sBLO + brow);
                mma_bf16(acc[0][2*p],   ah[0], ah[1], ah[2], ah[3], bh0, bh1);
                mma_bf16(acc[1][2*p],   ah[4], ah[5], ah[6], ah[7], bh0, bh1);
                mma_bf16(acc[0][2*p+1], ah[0], ah[1], ah[2], ah[3], bh2, bh3);
                mma_bf16(acc[1][2*p+1], ah[4], ah[5], ah[6], ah[7], bh2, bh3);
                mma_bf16(acc[0][2*p],   ah[0], ah[1], ah[2], ah[3], bl0, bl1);
                mma_bf16(acc[1][2*p],   ah[4], ah[5], ah[6], ah[7], bl0, bl1);
                mma_bf16(acc[0][2*p+1], ah[0], ah[1], ah[2], ah[3], bl2, bl3);
                mma_bf16(acc[1][2*p+1], ah[4], ah[5], ah[6], ah[7], bl2, bl3);
                mma_bf16(acc[0][2*p],   al[0], al[1], al[2], al[3], bh0, bh1);
                mma_bf16(acc[1][2*p],   al[4], al[5], al[6], al[7], bh0, bh1);
                mma_bf16(acc[0][2*p+1], al[0], al[1], al[2], al[3], bh2, bh3);
                mma_bf16(acc[1][2*p+1], al[4], al[5], al[6], al[7], bh2, bh3);
            }
        }
        __syncthreads();
    }

    // epilogue: fragments -> smem -> coalesced tanh/combine writes
    float* D = (float*)dynsm;          // 128 x 68 fp32
    #pragma unroll
    for (int ma = 0; ma < 2; ma++) {
        int row = rb*32 + ma*16 + g;
        #pragma unroll
        for (int na = 0; na < 4; na++) {
            int col = cb*32 + na*8 + 2*t;
            *(float2*)&D[row*68 + col]     = make_float2(acc[ma][na][0], acc[ma][na][1]);
            *(float2*)&D[(row+8)*68 + col] = make_float2(acc[ma][na][2], acc[ma][na][3]);
        }
    }
    __syncthreads();
    #pragma unroll
    for (int i = 0; i < 8; i++) {
        int f = tid + 256*i;           // 0..2047
        int r = f >> 4, c4 = f & 15;
        int col = c4*4;
        size_t m = (size_t)(m0 + r);
        int n = (int)(m >> 5);
        int b = (int)(m & 31);
        float4 v = *(const float4*)&D[r*68 + col];
        float4 b4 = *(const float4*)&bc[col];
        float cd0 = fast_tanh(v.x + b4.x);
        float cd1 = fast_tanh(v.y + b4.y);
        float cd2 = fast_tanh(v.z + b4.z);
        float cd3 = fast_tanh(v.w + b4.w);
        float4 z4 = *(const float4*)&g_Z[m*DOUT + col];
        float4 h4 = *(const float4*)&g_X[0][m*FF + 64 + col];
        float4 r4 = make_float4((1.f - z4.x)*h4.x + z4.x*cd0,
                                (1.f - z4.y)*h4.y + z4.y*cd1,
                                (1.f - z4.z)*h4.z + z4.z*cd2,
                                (1.f - z4.w)*h4.w + z4.w*cd3);
        *(float4*)&out[(size_t)b*(NN*DOUT) + (size_t)n*DOUT + col] = r4;
    }
}

// ---------------- launch ----------------
extern "C" void kernel_launch(void* const* d_in, const int* in_sizes, int n_in,
                              void* d_out, int out_size) {
    const float* inp = nullptr;
    const float* hx  = nullptr;
    const void*  ei  = nullptr;
    const float* ew  = nullptr;
    const float* Wg  = nullptr;
    const float* Wc  = nullptr;
    const float* bg  = nullptr;
    const float* bc  = nullptr;
    for (int i = 0; i < n_in; i++) {
        switch (in_sizes[i]) {
            case 20480000: if (!inp) inp = (const float*)d_in[i];
                           else      hx  = (const float*)d_in[i]; break;
            case 320000:   ei = d_in[i];                 break;
            case 160000:   ew = (const float*)d_in[i];   break;
            case 49152:    Wg = (const float*)d_in[i];   break;
            case 24576:    Wc = (const float*)d_in[i];   break;
            case 128:      bg = (const float*)d_in[i];   break;
            case 64:       bc = (const float*)d_in[i];   break;
            default: break;
        }
    }
    float* out = (float*)d_out;

    void *pX, *pH, *pXp, *pHp;
    cudaGetSymbolAddress(&pX, g_X);
    cudaGetSymbolAddress(&pH, g_H);
    cudaGetSymbolAddress(&pXp, g_Xp);
    cudaGetSymbolAddress(&pHp, g_Hp);
    float* X = (float*)pX;
    float* H = (float*)pH;
    __nv_bfloat16* Xp = (__nv_bfloat16*)pXp;   // [hi/lo][s][XPS]
    __nv_bfloat16* Hp = (__nv_bfloat16*)pHp;

    cudaFuncSetAttribute(k_gates_mma, cudaFuncAttributeMaxDynamicSharedMemorySize, 81920);
    cudaFuncSetAttribute(k_cand_mma,  cudaFuncAttributeMaxDynamicSharedMemorySize, 61440);

    // 1-3: CSR + X0 (+ planes) + weight planes
    k_histbuild<<<HIST_BLKS + NN + WPL_BLKS, 256>>>((const long long*)ei, inp, hx, Wg, Wc);
    k_scanfill<<<1, 1024>>>((const long long*)ei);
    k_fill<<<HIST_BLKS, 256>>>((const long long*)ei, ew);

    // 4-5: first diffusion (X1 fp32+planes; X2 planes only)
    dim3 gf(NN, 4);
    k_conv<V4F><<<gf, 256>>>((const float4*)X,          nullptr,
                             (float4*)(X + XPS),
                             Xp + 1*XPS, Xp + (3+1)*XPS, 1.f, 0);
    k_conv<V4F><<<gf, 256>>>((const float4*)(X + XPS),  (const float4*)X,
                             nullptr,
                             Xp + 2*XPS, Xp + (3+2)*XPS, 2.f, 1);

    // 6: gates GEMM -> z, RH (fp32 + planes)
    k_gates_mma<<<MM/128, 256, 81920>>>(bg);

    // 7-8: second diffusion on RH (D1 fp32+planes; D2 planes only)
    dim3 gh(NN, 2);
    k_conv<V4H><<<gh, 256>>>((const float4*)H,          nullptr,
                             (float4*)(H + HPS),
                             Hp + 1*HPS, Hp + (3+1)*HPS, 1.f, 0);
    k_conv<V4H><<<gh, 256>>>((const float4*)(H + HPS),  (const float4*)H,
                             nullptr,
                             Hp + 2*HPS, Hp + (3+2)*HPS, 2.f, 1);

    // 9: candidate GEMM + combine + transpose
    k_cand_mma<<<MM/128, 256, 61440>>>(bc, out);
}

// round 16
// speedup vs baseline: 1.2793x; 1.2671x over previous
#include <cuda_runtime.h>
#include <cuda_fp16.h>
#include <math.h>
#include <stdint.h>

// Problem constants (fixed by the reference)
#define NN   10000            // nodes
#define NB   32               // batch
#define DIN  64
#define DOUT 64
#define FF   128              // DIN + DOUT
#define NE   160000           // edges
#define MM   (NN*NB)          // 320000 rows (node-major: m = n*32 + b)
#define V4F  1024             // float4 per node (full width)
#define V4H  512              // float4 per node (half width)
#define XPS  ((size_t)MM*FF)   // X plane elems per stage
#define HPS  ((size_t)MM*DOUT) // H plane elems per stage

typedef unsigned long long u64;
typedef unsigned int u32;

// ---------------- scratch (device globals; allocation-free) ----------------
__device__ __align__(16) float g_X[2][XPS];    // X0, X1 fp32 (conv operands)
__device__ __align__(16) float g_H[2][HPS];    // RH, D1 fp32 (conv operands)
__device__ __align__(16) float g_Z[HPS];       // update gate z
__device__ __align__(16) __half g_Xp[3][XPS];  // fp16 planes (GEMM A operands)
__device__ __align__(16) __half g_Hp[3][HPS];
__device__ __align__(16) __half g_Wgp[128*384];
__device__ __align__(16) __half g_Wcp[64*384];
__device__ int    g_cnt[NN];
__device__ int    g_rs [NN+1];
__device__ int    g_cur[NN];
__device__ __align__(8) float2 g_epack[NE];   // {col as int bits, weight}

// ---------------- fp16 plane emit ----------------
__device__ __forceinline__ void emit_plane(float4 v, __half* p, size_t po) {
    __half2 h0 = __floats2half2_rn(v.x, v.y);
    __half2 h1 = __floats2half2_rn(v.z, v.w);
    *(uint2*)&p[po] = make_uint2(*(u32*)&h0, *(u32*)&h1);
}

__device__ __forceinline__ u32 smem_u32(const void* p) {
    u32 a;
    asm("{ .reg .u64 t; cvta.to.shared.u64 t, %1; cvt.u32.u64 %0, t; }"
        : "=r"(a) : "l"(p));
    return a;
}
__device__ __forceinline__ void cpa16(u32 dst, const void* src) {
    asm volatile("cp.async.ca.shared.global [%0], [%1], 16;"
                 :: "r"(dst), "l"(src) : "memory");
}
#define CP_COMMIT() asm volatile("cp.async.commit_group;" ::: "memory")
#define CP_WAIT1()  asm volatile("cp.async.wait_group 1;"  ::: "memory")
#define CP_WAIT0()  asm volatile("cp.async.wait_group 0;"  ::: "memory")

// ldmatrix x4: four 8x8 fp16 fragments in one instruction (sm_75+ family PTX)
__device__ __forceinline__ void ldsm4(u32& r0, u32& r1, u32& r2, u32& r3, u32 addr) {
    asm volatile("ldmatrix.sync.aligned.m8n8.x4.shared.b16 {%0,%1,%2,%3}, [%4];"
        : "=r"(r0), "=r"(r1), "=r"(r2), "=r"(r3) : "r"(addr));
}

// mma.sync m16n8k16 row.col f32.f16.f16.f32 (family PTX, sm_80+)
__device__ __forceinline__ void mma_fp16(float* c,
        u32 a0, u32 a1, u32 a2, u32 a3, u32 b0, u32 b1) {
    asm volatile("mma.sync.aligned.m16n8k16.row.col.f32.f16.f16.f32 "
        "{%0,%1,%2,%3}, {%4,%5,%6,%7}, {%8,%9}, {%0,%1,%2,%3};"
        : "+f"(c[0]), "+f"(c[1]), "+f"(c[2]), "+f"(c[3])
        : "r"(a0), "r"(a1), "r"(a2), "r"(a3), "r"(b0), "r"(b1));
}

// ---------------- fast activations ----------------
__device__ __forceinline__ float fast_sigmoid(float g) {
    return __fdividef(1.f, 1.f + __expf(-g));
}
__device__ __forceinline__ float fast_tanh(float x) {
    float t = __expf(-2.f * fabsf(x));
    float r = __fdividef(1.f - t, 1.f + t);
    return copysignf(r, x);
}

// ---------------- kernel 1: histogram / build X0+plane / weight planes --------
#define HIST_BLKS (NE/256)     // 625
#define WPL_BLKS  64
__global__ void k_histbuild(const long long* __restrict__ ei64,
                            const float* __restrict__ in,
                            const float* __restrict__ hx,
                            const float* __restrict__ Wg,
                            const float* __restrict__ Wc) {
    if (blockIdx.x < HIST_BLKS) {
        __shared__ int bad;
        if (threadIdx.x == 0) bad = 0;
        __syncthreads();
        long long v = ei64[threadIdx.x];
        if (v < 0 || v >= NN) atomicOr(&bad, 1);
        __syncthreads();
        int e = blockIdx.x*256 + threadIdx.x;
        int r;
        if (bad) r = ((const int*)ei64)[e];
        else     r = (int)ei64[e];
        atomicAdd(&g_cnt[r], 1);
    } else if (blockIdx.x < HIST_BLKS + NN) {
        int n = blockIdx.x - HIST_BLKS;
        const float4* in4 = (const float4*)in;
        const float4* hx4 = (const float4*)hx;
        for (int i = threadIdx.x; i < 512; i += 256) {
            int b = i >> 4, f4 = i & 15;
            size_t m = (size_t)n*32 + b;
            size_t po = m*FF + f4*4;
            float4 v = __ldg(&in4[((size_t)b*NN + n)*16 + f4]);
            *(float4*)&g_X[0][po] = v;
            emit_plane(v, g_Xp[0], po);
            float4 w = __ldg(&hx4[((size_t)b*NN + n)*16 + f4]);
            *(float4*)&g_X[0][po + 64] = w;
            emit_plane(w, g_Xp[0], po + 64);
        }
    } else {
        int j = blockIdx.x - (HIST_BLKS + NN);
        for (int e = j*768 + threadIdx.x; e < (j+1)*768; e += 256)
            g_Wgp[e] = __float2half(Wg[e]);
        for (int e = j*384 + threadIdx.x; e < (j+1)*384; e += 256)
            g_Wcp[e] = __float2half(Wc[e]);
    }
}

// ---------------- kernel 2: single-block scan + re-zero cnt ----------------
__global__ void k_scanfill(const long long* __restrict__ ei64) {
    __shared__ int sums[1024];
    int t = threadIdx.x;
    const int CH = 10;
    int base = t*CH;
    int loc[CH];
    int s = 0;
    #pragma unroll
    for (int i = 0; i < CH; i++) {
        int idx = base + i;
        int v = (idx < NN) ? g_cnt[idx] : 0;
        loc[i] = s; s += v;
    }
    sums[t] = s;
    __syncthreads();
    for (int off = 1; off < 1024; off <<= 1) {
        int v = (t >= off) ? sums[t-off] : 0;
        __syncthreads();
        sums[t] += v;
        __syncthreads();
    }
    int prev = (t > 0) ? sums[t-1] : 0;
    #pragma unroll
    for (int i = 0; i < CH; i++) {
        int idx = base + i;
        if (idx < NN) {
            int v = prev + loc[i];
            g_rs[idx] = v;
            g_cur[idx] = v;
        }
    }
    if (t == 1023) g_rs[NN] = sums[1023];
    __syncthreads();
    for (int i = t; i < NN; i += 1024) g_cnt[i] = 0;   // for next replay
}

// ---------------- kernel 3: CSR fill (multi-block, atomic cursors) ------------
__global__ void k_fill(const long long* __restrict__ ei64,
                       const float* __restrict__ ew) {
    __shared__ int bad;
    if (threadIdx.x == 0) bad = 0;
    __syncthreads();
    long long v = ei64[threadIdx.x];
    if (v < 0 || v >= NN) atomicOr(&bad, 1);
    __syncthreads();
    int e = blockIdx.x*256 + threadIdx.x;
    int r, c;
    if (bad) {
        r = ((const int*)ei64)[e];
        c = ((const int*)ei64)[NE + e];
    } else {
        r = (int)ei64[e];
        c = (int)ei64[NE + e];
    }
    int pos = atomicAdd(&g_cur[r], 1);
    g_epack[pos] = make_float2(__int_as_float(c), ew[e]);
}

// ---------------- graph conv (CSR gather-reduce, feature-sliced, 2-edge) -------
#define CONV_FMA(acc, p, v) \
    acc.x = fmaf(p.y, v.x, acc.x); acc.y = fmaf(p.y, v.y, acc.y); \
    acc.z = fmaf(p.y, v.z, acc.z); acc.w = fmaf(p.y, v.w, acc.w);

template<int NV4>
__global__ __launch_bounds__(256) void k_conv(const float4* __restrict__ x,
                       const float4* __restrict__ base,
                       float4* __restrict__ out,
                       __half* __restrict__ php,
                       float scale, int sub) {
    int n   = blockIdx.x;
    int idx = blockIdx.y*256 + threadIdx.x;
    const float4* xb = x + idx;
    float4 acc = make_float4(0.f, 0.f, 0.f, 0.f);
    int e0 = __ldg(&g_rs[n]);
    int e1 = __ldg(&g_rs[n+1]);
    int e = e0;
    for (; e + 2 <= e1; e += 2) {
        float2 p0 = __ldg(&g_epack[e]);
        float2 p1 = __ldg(&g_epack[e+1]);
        float4 v0 = __ldg(xb + __float_as_int(p0.x)*NV4);
        float4 v1 = __ldg(xb + __float_as_int(p1.x)*NV4);
        CONV_FMA(acc, p0, v0)
        CONV_FMA(acc, p1, v1)
    }
    if (e < e1) {
        float2 p0 = __ldg(&g_epack[e]);
        float4 v0 = __ldg(xb + __float_as_int(p0.x)*NV4);
        CONV_FMA(acc, p0, v0)
    }
    float4 r;
    if (sub) {
        float4 b = __ldg(&base[n*NV4 + idx]);
        r = make_float4(fmaf(scale, acc.x, -b.x), fmaf(scale, acc.y, -b.y),
                        fmaf(scale, acc.z, -b.z), fmaf(scale, acc.w, -b.w));
    } else {
        r = make_float4(scale*acc.x, scale*acc.y, scale*acc.z, scale*acc.w);
    }
    if (out) __stcs(&out[n*NV4 + idx], r);
    const int KW  = NV4/8;         // 128 or 64
    const int KW4 = KW/4;
    int b  = idx / KW4;
    int f4 = idx % KW4;
    size_t po = ((size_t)n*32 + b)*KW + f4*4;
    emit_plane(r, php, po);
}

// ================= GEMM 1: gates (fp16 single-pass, k32 double buffer) =========
// 12 sub-chunks of K=32. Stage buffer (20480 B): A 0 (128x80), B 10240 (128x80).
// 2 stages = 40960 B; epilogue D tile 128x132 fp32 = 67584 B (dyn smem size).
extern __shared__ char dynsm[];

__device__ __forceinline__ void gates_stage(int c, int buf, int m0, int tid, u32 sb) {
    u32 base = sb + buf*20480;
    const __half* Ah = &g_Xp[c >> 2][(c & 3)*32];
    int wcol = c*32;
    #pragma unroll
    for (int i = 0; i < 2; i++) {
        int f = tid + 256*i;           // 0..511
        int r = f >> 2, q = f & 3;
        u32 d = r*80 + q*16;
        cpa16(base + d,         Ah + (size_t)(m0 + r)*FF + q*8);
        cpa16(base + 10240 + d, &g_Wgp[r*384 + wcol + q*8]);
    }
}

__global__ __launch_bounds__(256, 2)
void k_gates_mma(const float* __restrict__ bg) {
    u32 sb = smem_u32(dynsm);
    int tid = threadIdx.x, wid = tid >> 5, lid = tid & 31;
    int g = lid >> 2, t = lid & 3;
    int m0 = blockIdx.x * 128;
    int rb = wid & 3, cb = wid >> 2;

    float acc[2][8][4];
    #pragma unroll
    for (int i = 0; i < 2; i++)
        #pragma unroll
        for (int j = 0; j < 8; j++)
            #pragma unroll
            for (int k = 0; k < 4; k++) acc[i][j][k] = 0.f;

    u32 a_row = (u32)(lid & 15);
    u32 a_kh  = (u32)(lid >> 4) * 16;
    u32 b_row = (u32)((lid & 7) + ((lid & 16) ? 8 : 0));
    u32 b_kh  = (lid & 8) ? 16u : 0u;

    gates_stage(0, 0, m0, tid, sb);
    CP_COMMIT();

    #pragma unroll 1
    for (int c = 0; c < 12; c++) {
        if (c < 11) {
            gates_stage(c+1, (c+1)&1, m0, tid, sb);
            CP_COMMIT();
            CP_WAIT1();
        } else {
            CP_WAIT0();
        }
        __syncthreads();
        u32 B0 = sb + (c&1)*20480;
        u32 sA = B0, sB = B0 + 10240;
        #pragma unroll
        for (int ks = 0; ks < 2; ks++) {
            u32 kb = ks*32 + a_kh;
            u32 a0, a1, a2, a3, a4, a5, a6, a7;
            ldsm4(a0, a1, a2, a3, sA + (rb*32 + a_row)*80 + kb);
            ldsm4(a4, a5, a6, a7, sA + (rb*32 + 16 + a_row)*80 + kb);
            u32 kbb = ks*32 + b_kh;
            #pragma unroll
            for (int p = 0; p < 4; p++) {
                u32 b0, b1, b2, b3;
                ldsm4(b0, b1, b2, b3, sB + (cb*64 + p*16 + b_row)*80 + kbb);
                mma_fp16(acc[0][2*p],   a0, a1, a2, a3, b0, b1);
                mma_fp16(acc[1][2*p],   a4, a5, a6, a7, b0, b1);
                mma_fp16(acc[0][2*p+1], a0, a1, a2, a3, b2, b3);
                mma_fp16(acc[1][2*p+1], a4, a5, a6, a7, b2, b3);
            }
        }
        __syncthreads();
    }

    // epilogue: fragments -> smem D tile -> coalesced sigmoid writes
    float* D = (float*)dynsm;          // 128 x 132 fp32
    #pragma unroll
    for (int ma = 0; ma < 2; ma++) {
        int row = rb*32 + ma*16 + g;
        #pragma unroll
        for (int na = 0; na < 8; na++) {
            int col = cb*64 + na*8 + 2*t;
            *(float2*)&D[row*132 + col]     = make_float2(acc[ma][na][0], acc[ma][na][1]);
            *(float2*)&D[(row+8)*132 + col] = make_float2(acc[ma][na][2], acc[ma][na][3]);
        }
    }
    __syncthreads();
    #pragma unroll
    for (int i = 0; i < 16; i++) {
        int f = tid + 256*i;           // 0..4095
        int r = f >> 5, c4 = f & 31;
        int col = c4*4;
        size_t m = (size_t)(m0 + r);
        float4 v = *(const float4*)&D[r*132 + col];
        float4 b4 = *(const float4*)&bg[col];
        float s0 = fast_sigmoid(v.x + b4.x);
        float s1 = fast_sigmoid(v.y + b4.y);
        float s2 = fast_sigmoid(v.z + b4.z);
        float s3 = fast_sigmoid(v.w + b4.w);
        if (col < 64) {
            *(float4*)&g_Z[m*DOUT + col] = make_float4(s0, s1, s2, s3);
        } else {
            float4 hv = *(const float4*)&g_X[0][m*FF + col];
            float4 rh = make_float4(s0*hv.x, s1*hv.y, s2*hv.z, s3*hv.w);
            size_t po = m*DOUT + (col - 64);
            *(float4*)&g_H[0][po] = rh;
            emit_plane(rh, g_Hp[0], po);
        }
    }
}

// ================= GEMM 2: candidate (fp16 single-pass) + combine ==============
// Stage buffer (15360 B): A 0 (128x80), B 10240 (64x80).
// 2 stages = 30720; epilogue D 128x68 fp32 = 34816 (dyn smem size). occ 3.
__device__ __forceinline__ void cand_stage(int c, int buf, int m0, int tid, u32 sb) {
    u32 base = sb + buf*15360;
    int c2 = c >> 1;
    const __half* Ah;
    int rs;
    if ((c2 & 1) == 0) { Ah = &g_Xp[c2 >> 1][(c & 1)*32]; rs = FF; }
    else               { Ah = &g_Hp[c2 >> 1][(c & 1)*32]; rs = DOUT; }
    int wcol = c*32;
    #pragma unroll
    for (int i = 0; i < 2; i++) {
        int f = tid + 256*i;
        int r = f >> 2, q = f & 3;
        cpa16(base + r*80 + q*16, Ah + (size_t)(m0 + r)*rs + q*8);
    }
    if (tid < 256) {                   // B: 64 rows x 4 chunks = 256
        int r = tid >> 2, q = tid & 3;
        cpa16(base + 10240 + r*80 + q*16, &g_Wcp[r*384 + wcol + q*8]);
    }
}

__global__ __launch_bounds__(256, 3)
void k_cand_mma(const float* __restrict__ bc, float* __restrict__ out) {
    u32 sb = smem_u32(dynsm);
    int tid = threadIdx.x, wid = tid >> 5, lid = tid & 31;
    int g = lid >> 2, t = lid & 3;
    int m0 = blockIdx.x * 128;
    int rb = wid & 3, cb = wid >> 2;

    float acc[2][4][4];
    #pragma unroll
    for (int i = 0; i < 2; i++)
        #pragma unroll
        for (int j = 0; j < 4; j++)
            #pragma unroll
            for (int k = 0; k < 4; k++) acc[i][j][k] = 0.f;

    u32 a_row = (u32)(lid & 15);
    u32 a_kh  = (u32)(lid >> 4) * 16;
    u32 b_row = (u32)((lid & 7) + ((lid & 16) ? 8 : 0));
    u32 b_kh  = (lid & 8) ? 16u : 0u;

    cand_stage(0, 0, m0, tid, sb);
    CP_COMMIT();

    #pragma unroll 1
    for (int c = 0; c < 12; c++) {
        if (c < 11) {
            cand_stage(c+1, (c+1)&1, m0, tid, sb);
            CP_COMMIT();
            CP_WAIT1();
        } else {
            CP_WAIT0();
        }
        __syncthreads();
        u32 B0 = sb + (c&1)*15360;
        u32 sA = B0, sB = B0 + 10240;
        #pragma unroll
        for (int ks = 0; ks < 2; ks++) {
            u32 kb = ks*32 + a_kh;
            u32 a0, a1, a2, a3, a4, a5, a6, a7;
            ldsm4(a0, a1, a2, a3, sA + (rb*32 + a_row)*80 + kb);
            ldsm4(a4, a5, a6, a7, sA + (rb*32 + 16 + a_row)*80 + kb);
            u32 kbb = ks*32 + b_kh;
            #pragma unroll
            for (int p = 0; p < 2; p++) {
                u32 b0, b1, b2, b3;
                ldsm4(b0, b1, b2, b3, sB + (cb*32 + p*16 + b_row)*80 + kbb);
                mma_fp16(acc[0][2*p],   a0, a1, a2, a3, b0, b1);
                mma_fp16(acc[1][2*p],   a4, a5, a6, a7, b0, b1);
                mma_fp16(acc[0][2*p+1], a0, a1, a2, a3, b2, b3);
                mma_fp16(acc[1][2*p+1], a4, a5, a6, a7, b2, b3);
            }
        }
        __syncthreads();
    }

    // epilogue: fragments -> smem -> coalesced tanh/combine writes
    float* D = (float*)dynsm;          // 128 x 68 fp32
    #pragma unroll
    for (int ma = 0; ma < 2; ma++) {
        int row = rb*32 + ma*16 + g;
        #pragma unroll
        for (int na = 0; na < 4; na++) {
            int col = cb*32 + na*8 + 2*t;
            *(float2*)&D[row*68 + col]     = make_float2(acc[ma][na][0], acc[ma][na][1]);
            *(float2*)&D[(row+8)*68 + col] = make_float2(acc[ma][na][2], acc[ma][na][3]);
        }
    }
    __syncthreads();
    #pragma unroll
    for (int i = 0; i < 8; i++) {
        int f = tid + 256*i;           // 0..2047
        int r = f >> 4, c4 = f & 15;
        int col = c4*4;
        size_t m = (size_t)(m0 + r);
        int n = (int)(m >> 5);
        int b = (int)(m & 31);
        float4 v = *(const float4*)&D[r*68 + col];
        float4 b4 = *(const float4*)&bc[col];
        float cd0 = fast_tanh(v.x + b4.x);
        float cd1 = fast_tanh(v.y + b4.y);
        float cd2 = fast_tanh(v.z + b4.z);
        float cd3 = fast_tanh(v.w + b4.w);
        float4 z4 = *(const float4*)&g_Z[m*DOUT + col];
        float4 h4 = *(const float4*)&g_X[0][m*FF + 64 + col];
        float4 r4 = make_float4((1.f - z4.x)*h4.x + z4.x*cd0,
                                (1.f - z4.y)*h4.y + z4.y*cd1,
                                (1.f - z4.z)*h4.z + z4.z*cd2,
                                (1.f - z4.w)*h4.w + z4.w*cd3);
        *(float4*)&out[(size_t)b*(NN*DOUT) + (size_t)n*DOUT + col] = r4;
    }
}

// ---------------- launch ----------------
extern "C" void kernel_launch(void* const* d_in, const int* in_sizes, int n_in,
                              void* d_out, int out_size) {
    const float* inp = nullptr;
    const float* hx  = nullptr;
    const void*  ei  = nullptr;
    const float* ew  = nullptr;
    const float* Wg  = nullptr;
    const float* Wc  = nullptr;
    const float* bg  = nullptr;
    const float* bc  = nullptr;
    for (int i = 0; i < n_in; i++) {
        switch (in_sizes[i]) {
            case 20480000: if (!inp) inp = (const float*)d_in[i];
                           else      hx  = (const float*)d_in[i]; break;
            case 320000:   ei = d_in[i];                 break;
            case 160000:   ew = (const float*)d_in[i];   break;
            case 49152:    Wg = (const float*)d_in[i];   break;
            case 24576:    Wc = (const float*)d_in[i];   break;
            case 128:      bg = (const float*)d_in[i];   break;
            case 64:       bc = (const float*)d_in[i];   break;
            default: break;
        }
    }
    float* out = (float*)d_out;

    void *pX, *pH, *pXp, *pHp;
    cudaGetSymbolAddress(&pX, g_X);
    cudaGetSymbolAddress(&pH, g_H);
    cudaGetSymbolAddress(&pXp, g_Xp);
    cudaGetSymbolAddress(&pHp, g_Hp);
    float* X = (float*)pX;
    float* H = (float*)pH;
    __half* Xp = (__half*)pXp;   // [stage][XPS]
    __half* Hp = (__half*)pHp;

    cudaFuncSetAttribute(k_gates_mma, cudaFuncAttributeMaxDynamicSharedMemorySize, 67584);
    cudaFuncSetAttribute(k_cand_mma,  cudaFuncAttributeMaxDynamicSharedMemorySize, 34816);

    // 1-3: CSR + X0 (+ plane) + weight planes
    k_histbuild<<<HIST_BLKS + NN + WPL_BLKS, 256>>>((const long long*)ei, inp, hx, Wg, Wc);
    k_scanfill<<<1, 1024>>>((const long long*)ei);
    k_fill<<<HIST_BLKS, 256>>>((const long long*)ei, ew);

    // 4-5: first diffusion (X1 fp32+plane; X2 plane only)
    dim3 gf(NN, 4);
    k_conv<V4F><<<gf, 256>>>((const float4*)X,          nullptr,
                             (float4*)(X + XPS),
                             Xp + 1*XPS, 1.f, 0);
    k_conv<V4F><<<gf, 256>>>((const float4*)(X + XPS),  (const float4*)X,
                             nullptr,
                             Xp + 2*XPS, 2.f, 1);

    // 6: gates GEMM -> z, RH (fp32 + plane)
    k_gates_mma<<<MM/128, 256, 67584>>>(bg);

    // 7-8: second diffusion on RH (D1 fp32+plane; D2 plane only)
    dim3 gh(NN, 2);
    k_conv<V4H><<<gh, 256>>>((const float4*)H,          nullptr,
                             (float4*)(H + HPS),
                             Hp + 1*HPS, 1.f, 0);
    k_conv<V4H><<<gh, 256>>>((const float4*)(H + HPS),  (const float4*)H,
                             nullptr,
                             Hp + 2*HPS, 2.f, 1);

    // 9: candidate GEMM + combine + transpose
    k_cand_mma<<<MM/128, 256, 34816>>>(bc, out);
}

// round 17
// speedup vs baseline: 1.4953x; 1.1689x over previous
#include <cuda_runtime.h>
#include <cuda_fp16.h>
#include <math.h>
#include <stdint.h>

// Problem constants (fixed by the reference)
#define NN   10000            // nodes
#define NB   32               // batch
#define DIN  64
#define DOUT 64
#define FF   128              // DIN + DOUT
#define NE   160000           // edges
#define MM   (NN*NB)          // 320000 rows (node-major: m = n*32 + b)
#define XPS  ((size_t)MM*FF)   // X plane elems per stage
#define HPS  ((size_t)MM*DOUT) // H plane elems per stage

typedef unsigned long long u64;
typedef unsigned int u32;

// ---------------- scratch (device globals; allocation-free) ----------------
__device__ __align__(16) float g_X0[XPS];      // concat(inputs,hx) fp32 (epilogues + cheb base)
__device__ __align__(16) float g_RH[HPS];      // r*hx fp32 (cheb base)
__device__ __align__(16) float g_Z[HPS];       // update gate z
__device__ __align__(16) __half g_Xp[3][XPS];  // fp16 planes (conv + GEMM operands)
__device__ __align__(16) __half g_Hp[3][HPS];
__device__ __align__(16) __half g_Wgp[128*384];
__device__ __align__(16) __half g_Wcp[64*384];
__device__ int    g_cnt[NN];
__device__ int    g_rs [NN+1];
__device__ int    g_cur[NN];
__device__ __align__(8) float2 g_epack[NE];   // {col as int bits, weight}

// ---------------- fp16 plane emit ----------------
__device__ __forceinline__ void emit_plane(float4 v, __half* p, size_t po) {
    __half2 h0 = __floats2half2_rn(v.x, v.y);
    __half2 h1 = __floats2half2_rn(v.z, v.w);
    *(uint2*)&p[po] = make_uint2(*(u32*)&h0, *(u32*)&h1);
}

__device__ __forceinline__ u32 smem_u32(const void* p) {
    u32 a;
    asm("{ .reg .u64 t; cvta.to.shared.u64 t, %1; cvt.u32.u64 %0, t; }"
        : "=r"(a) : "l"(p));
    return a;
}
__device__ __forceinline__ void cpa16(u32 dst, const void* src) {
    asm volatile("cp.async.ca.shared.global [%0], [%1], 16;"
                 :: "r"(dst), "l"(src) : "memory");
}
#define CP_COMMIT() asm volatile("cp.async.commit_group;" ::: "memory")
#define CP_WAIT1()  asm volatile("cp.async.wait_group 1;"  ::: "memory")
#define CP_WAIT0()  asm volatile("cp.async.wait_group 0;"  ::: "memory")

// ldmatrix x4 (sm_75+ family PTX)
__device__ __forceinline__ void ldsm4(u32& r0, u32& r1, u32& r2, u32& r3, u32 addr) {
    asm volatile("ldmatrix.sync.aligned.m8n8.x4.shared.b16 {%0,%1,%2,%3}, [%4];"
        : "=r"(r0), "=r"(r1), "=r"(r2), "=r"(r3) : "r"(addr));
}

// mma.sync m16n8k16 row.col f32.f16.f16.f32 (family PTX, sm_80+)
__device__ __forceinline__ void mma_fp16(float* c,
        u32 a0, u32 a1, u32 a2, u32 a3, u32 b0, u32 b1) {
    asm volatile("mma.sync.aligned.m16n8k16.row.col.f32.f16.f16.f32 "
        "{%0,%1,%2,%3}, {%4,%5,%6,%7}, {%8,%9}, {%0,%1,%2,%3};"
        : "+f"(c[0]), "+f"(c[1]), "+f"(c[2]), "+f"(c[3])
        : "r"(a0), "r"(a1), "r"(a2), "r"(a3), "r"(b0), "r"(b1));
}

// ---------------- fast activations ----------------
__device__ __forceinline__ float fast_sigmoid(float g) {
    return __fdividef(1.f, 1.f + __expf(-g));
}
__device__ __forceinline__ float fast_tanh(float x) {
    float t = __expf(-2.f * fabsf(x));
    float r = __fdividef(1.f - t, 1.f + t);
    return copysignf(r, x);
}

// ---------------- kernel 1: histogram / build X0+plane / weight planes --------
#define HIST_BLKS (NE/256)     // 625
#define WPL_BLKS  64
__global__ void k_histbuild(const long long* __restrict__ ei64,
                            const float* __restrict__ in,
                            const float* __restrict__ hx,
                            const float* __restrict__ Wg,
                            const float* __restrict__ Wc) {
    if (blockIdx.x < HIST_BLKS) {
        __shared__ int bad;
        if (threadIdx.x == 0) bad = 0;
        __syncthreads();
        long long v = ei64[threadIdx.x];
        if (v < 0 || v >= NN) atomicOr(&bad, 1);
        __syncthreads();
        int e = blockIdx.x*256 + threadIdx.x;
        int r;
        if (bad) r = ((const int*)ei64)[e];
        else     r = (int)ei64[e];
        atomicAdd(&g_cnt[r], 1);
    } else if (blockIdx.x < HIST_BLKS + NN) {
        int n = blockIdx.x - HIST_BLKS;
        const float4* in4 = (const float4*)in;
        const float4* hx4 = (const float4*)hx;
        for (int i = threadIdx.x; i < 512; i += 256) {
            int b = i >> 4, f4 = i & 15;
            size_t m = (size_t)n*32 + b;
            size_t po = m*FF + f4*4;
            float4 v = __ldg(&in4[((size_t)b*NN + n)*16 + f4]);
            *(float4*)&g_X0[po] = v;
            emit_plane(v, g_Xp[0], po);
            float4 w = __ldg(&hx4[((size_t)b*NN + n)*16 + f4]);
            *(float4*)&g_X0[po + 64] = w;
            emit_plane(w, g_Xp[0], po + 64);
        }
    } else {
        int j = blockIdx.x - (HIST_BLKS + NN);
        for (int e = j*768 + threadIdx.x; e < (j+1)*768; e += 256)
            g_Wgp[e] = __float2half(Wg[e]);
        for (int e = j*384 + threadIdx.x; e < (j+1)*384; e += 256)
            g_Wcp[e] = __float2half(Wc[e]);
    }
}

// ---------------- kernel 2: single-block scan + re-zero cnt ----------------
__global__ void k_scanfill(const long long* __restrict__ ei64) {
    __shared__ int sums[1024];
    int t = threadIdx.x;
    const int CH = 10;
    int base = t*CH;
    int loc[CH];
    int s = 0;
    #pragma unroll
    for (int i = 0; i < CH; i++) {
        int idx = base + i;
        int v = (idx < NN) ? g_cnt[idx] : 0;
        loc[i] = s; s += v;
    }
    sums[t] = s;
    __syncthreads();
    for (int off = 1; off < 1024; off <<= 1) {
        int v = (t >= off) ? sums[t-off] : 0;
        __syncthreads();
        sums[t] += v;
        __syncthreads();
    }
    int prev = (t > 0) ? sums[t-1] : 0;
    #pragma unroll
    for (int i = 0; i < CH; i++) {
        int idx = base + i;
        if (idx < NN) {
            int v = prev + loc[i];
            g_rs[idx] = v;
            g_cur[idx] = v;
        }
    }
    if (t == 1023) g_rs[NN] = sums[1023];
    __syncthreads();
    for (int i = t; i < NN; i += 1024) g_cnt[i] = 0;   // for next replay
}

// ---------------- kernel 3: CSR fill (multi-block, atomic cursors) ------------
__global__ void k_fill(const long long* __restrict__ ei64,
                       const float* __restrict__ ew) {
    __shared__ int bad;
    if (threadIdx.x == 0) bad = 0;
    __syncthreads();
    long long v = ei64[threadIdx.x];
    if (v < 0 || v >= NN) atomicOr(&bad, 1);
    __syncthreads();
    int e = blockIdx.x*256 + threadIdx.x;
    int r, c;
    if (bad) {
        r = ((const int*)ei64)[e];
        c = ((const int*)ei64)[NE + e];
    } else {
        r = (int)ei64[e];
        c = (int)ei64[NE + e];
    }
    int pos = atomicAdd(&g_cur[r], 1);
    g_epack[pos] = make_float2(__int_as_float(c), ew[e]);
}

// ---------------- graph conv: fp16 gather, fp32 accumulate, fp16 plane out -----
// out[n] = round_fp16( scale * sum w_e * xp[col_e]  - (sub ? base[n] : 0) )
// KW feats per (n,b) row; thread handles 8 feats (one uint4 of plane).
#define CVT_FMA(w, h2, a0, a1) { \
    float2 f_ = __half22float2(h2); \
    a0 = fmaf(w, f_.x, a0); a1 = fmaf(w, f_.y, a1); }

template<int KW>
__global__ __launch_bounds__(256) void k_conv_h(const uint4* __restrict__ xp,
                       const float4* __restrict__ base,
                       uint4* __restrict__ outp,
                       float scale, int sub) {
    const int NU4 = KW*4;              // uint4 per node (512 full, 256 half)
    int n   = blockIdx.x;
    int idx = blockIdx.y*256 + threadIdx.x;
    const uint4* xb = xp + idx;
    float a0=0.f,a1=0.f,a2=0.f,a3=0.f,a4=0.f,a5=0.f,a6=0.f,a7=0.f;
    int e0 = __ldg(&g_rs[n]);
    int e1 = __ldg(&g_rs[n+1]);
    int e = e0;
    for (; e + 2 <= e1; e += 2) {
        float2 p0 = __ldg(&g_epack[e]);
        float2 p1 = __ldg(&g_epack[e+1]);
        uint4 v0 = __ldg(xb + __float_as_int(p0.x)*NU4);
        uint4 v1 = __ldg(xb + __float_as_int(p1.x)*NU4);
        const __half2* h0 = (const __half2*)&v0;
        const __half2* h1 = (const __half2*)&v1;
        CVT_FMA(p0.y, h0[0], a0, a1)
        CVT_FMA(p0.y, h0[1], a2, a3)
        CVT_FMA(p0.y, h0[2], a4, a5)
        CVT_FMA(p0.y, h0[3], a6, a7)
        CVT_FMA(p1.y, h1[0], a0, a1)
        CVT_FMA(p1.y, h1[1], a2, a3)
        CVT_FMA(p1.y, h1[2], a4, a5)
        CVT_FMA(p1.y, h1[3], a6, a7)
    }
    if (e < e1) {
        float2 p0 = __ldg(&g_epack[e]);
        uint4 v0 = __ldg(xb + __float_as_int(p0.x)*NU4);
        const __half2* h0 = (const __half2*)&v0;
        CVT_FMA(p0.y, h0[0], a0, a1)
        CVT_FMA(p0.y, h0[1], a2, a3)
        CVT_FMA(p0.y, h0[2], a4, a5)
        CVT_FMA(p0.y, h0[3], a6, a7)
    }
    if (sub) {
        float4 b0 = __ldg(&base[(size_t)n*KW*8 + 2*idx]);
        float4 b1 = __ldg(&base[(size_t)n*KW*8 + 2*idx + 1]);
        a0 = fmaf(scale, a0, -b0.x); a1 = fmaf(scale, a1, -b0.y);
        a2 = fmaf(scale, a2, -b0.z); a3 = fmaf(scale, a3, -b0.w);
        a4 = fmaf(scale, a4, -b1.x); a5 = fmaf(scale, a5, -b1.y);
        a6 = fmaf(scale, a6, -b1.z); a7 = fmaf(scale, a7, -b1.w);
    } else {
        a0 *= scale; a1 *= scale; a2 *= scale; a3 *= scale;
        a4 *= scale; a5 *= scale; a6 *= scale; a7 *= scale;
    }
    __half2 o0 = __floats2half2_rn(a0, a1);
    __half2 o1 = __floats2half2_rn(a2, a3);
    __half2 o2 = __floats2half2_rn(a4, a5);
    __half2 o3 = __floats2half2_rn(a6, a7);
    outp[(size_t)n*NU4 + idx] =
        make_uint4(*(u32*)&o0, *(u32*)&o1, *(u32*)&o2, *(u32*)&o3);
}

// ================= GEMM 1: gates (fp16 single-pass, k32 double buffer) =========
// Stage buffer (20480 B): A 0 (128x80), B 10240 (128x80). 2 stages = 40960 B;
// epilogue D tile 128x132 fp32 = 67584 B (dyn smem size).
extern __shared__ char dynsm[];

__device__ __forceinline__ void gates_stage(int c, int buf, int m0, int tid, u32 sb) {
    u32 base = sb + buf*20480;
    const __half* Ah = &g_Xp[c >> 2][(c & 3)*32];
    int wcol = c*32;
    #pragma unroll
    for (int i = 0; i < 2; i++) {
        int f = tid + 256*i;           // 0..511
        int r = f >> 2, q = f & 3;
        u32 d = r*80 + q*16;
        cpa16(base + d,         Ah + (size_t)(m0 + r)*FF + q*8);
        cpa16(base + 10240 + d, &g_Wgp[r*384 + wcol + q*8]);
    }
}

__global__ __launch_bounds__(256, 2)
void k_gates_mma(const float* __restrict__ bg) {
    u32 sb = smem_u32(dynsm);
    int tid = threadIdx.x, wid = tid >> 5, lid = tid & 31;
    int g = lid >> 2, t = lid & 3;
    int m0 = blockIdx.x * 128;
    int rb = wid & 3, cb = wid >> 2;

    float acc[2][8][4];
    #pragma unroll
    for (int i = 0; i < 2; i++)
        #pragma unroll
        for (int j = 0; j < 8; j++)
            #pragma unroll
            for (int k = 0; k < 4; k++) acc[i][j][k] = 0.f;

    u32 a_row = (u32)(lid & 15);
    u32 a_kh  = (u32)(lid >> 4) * 16;
    u32 b_row = (u32)((lid & 7) + ((lid & 16) ? 8 : 0));
    u32 b_kh  = (lid & 8) ? 16u : 0u;

    gates_stage(0, 0, m0, tid, sb);
    CP_COMMIT();

    #pragma unroll 1
    for (int c = 0; c < 12; c++) {
        if (c < 11) {
            gates_stage(c+1, (c+1)&1, m0, tid, sb);
            CP_COMMIT();
            CP_WAIT1();
        } else {
            CP_WAIT0();
        }
        __syncthreads();
        u32 B0 = sb + (c&1)*20480;
        u32 sA = B0, sB = B0 + 10240;
        #pragma unroll
        for (int ks = 0; ks < 2; ks++) {
            u32 kb = ks*32 + a_kh;
            u32 a0, a1, a2, a3, a4, a5, a6, a7;
            ldsm4(a0, a1, a2, a3, sA + (rb*32 + a_row)*80 + kb);
            ldsm4(a4, a5, a6, a7, sA + (rb*32 + 16 + a_row)*80 + kb);
            u32 kbb = ks*32 + b_kh;
            #pragma unroll
            for (int p = 0; p < 4; p++) {
                u32 b0, b1, b2, b3;
                ldsm4(b0, b1, b2, b3, sB + (cb*64 + p*16 + b_row)*80 + kbb);
                mma_fp16(acc[0][2*p],   a0, a1, a2, a3, b0, b1);
                mma_fp16(acc[1][2*p],   a4, a5, a6, a7, b0, b1);
                mma_fp16(acc[0][2*p+1], a0, a1, a2, a3, b2, b3);
                mma_fp16(acc[1][2*p+1], a4, a5, a6, a7, b2, b3);
            }
        }
        __syncthreads();
    }

    // epilogue: fragments -> smem D tile -> coalesced sigmoid writes
    float* D = (float*)dynsm;          // 128 x 132 fp32
    #pragma unroll
    for (int ma = 0; ma < 2; ma++) {
        int row = rb*32 + ma*16 + g;
        #pragma unroll
        for (int na = 0; na < 8; na++) {
            int col = cb*64 + na*8 + 2*t;
            *(float2*)&D[row*132 + col]     = make_float2(acc[ma][na][0], acc[ma][na][1]);
            *(float2*)&D[(row+8)*132 + col] = make_float2(acc[ma][na][2], acc[ma][na][3]);
        }
    }
    __syncthreads();
    #pragma unroll
    for (int i = 0; i < 16; i++) {
        int f = tid + 256*i;           // 0..4095
        int r = f >> 5, c4 = f & 31;
        int col = c4*4;
        size_t m = (size_t)(m0 + r);
        float4 v = *(const float4*)&D[r*132 + col];
        float4 b4 = *(const float4*)&bg[col];
        float s0 = fast_sigmoid(v.x + b4.x);
        float s1 = fast_sigmoid(v.y + b4.y);
        float s2 = fast_sigmoid(v.z + b4.z);
        float s3 = fast_sigmoid(v.w + b4.w);
        if (col < 64) {
            *(float4*)&g_Z[m*DOUT + col] = make_float4(s0, s1, s2, s3);
        } else {
            float4 hv = *(const float4*)&g_X0[m*FF + col];
            float4 rh = make_float4(s0*hv.x, s1*hv.y, s2*hv.z, s3*hv.w);
            size_t po = m*DOUT + (col - 64);
            *(float4*)&g_RH[po] = rh;
            emit_plane(rh, g_Hp[0], po);
        }
    }
}

// ================= GEMM 2: candidate (fp16 single-pass) + combine ==============
// Stage buffer (15360 B): A 0 (128x80), B 10240 (64x80). 2 stages = 30720;
// epilogue D 128x68 fp32 = 34816 (dyn smem size). occ 3.
__device__ __forceinline__ void cand_stage(int c, int buf, int m0, int tid, u32 sb) {
    u32 base = sb + buf*15360;
    int c2 = c >> 1;
    const __half* Ah;
    int rs;
    if ((c2 & 1) == 0) { Ah = &g_Xp[c2 >> 1][(c & 1)*32]; rs = FF; }
    else               { Ah = &g_Hp[c2 >> 1][(c & 1)*32]; rs = DOUT; }
    int wcol = c*32;
    #pragma unroll
    for (int i = 0; i < 2; i++) {
        int f = tid + 256*i;
        int r = f >> 2, q = f & 3;
        cpa16(base + r*80 + q*16, Ah + (size_t)(m0 + r)*rs + q*8);
    }
    if (tid < 256) {
        int r = tid >> 2, q = tid & 3;
        cpa16(base + 10240 + r*80 + q*16, &g_Wcp[r*384 + wcol + q*8]);
    }
}

__global__ __launch_bounds__(256, 3)
void k_cand_mma(const float* __restrict__ bc, float* __restrict__ out) {
    u32 sb = smem_u32(dynsm);
    int tid = threadIdx.x, wid = tid >> 5, lid = tid & 31;
    int g = lid >> 2, t = lid & 3;
    int m0 = blockIdx.x * 128;
    int rb = wid & 3, cb = wid >> 2;

    float acc[2][4][4];
    #pragma unroll
    for (int i = 0; i < 2; i++)
        #pragma unroll
        for (int j = 0; j < 4; j++)
            #pragma unroll
            for (int k = 0; k < 4; k++) acc[i][j][k] = 0.f;

    u32 a_row = (u32)(lid & 15);
    u32 a_kh  = (u32)(lid >> 4) * 16;
    u32 b_row = (u32)((lid & 7) + ((lid & 16) ? 8 : 0));
    u32 b_kh  = (lid & 8) ? 16u : 0u;

    cand_stage(0, 0, m0, tid, sb);
    CP_COMMIT();

    #pragma unroll 1
    for (int c = 0; c < 12; c++) {
        if (c < 11) {
            cand_stage(c+1, (c+1)&1, m0, tid, sb);
            CP_COMMIT();
            CP_WAIT1();
        } else {
            CP_WAIT0();
        }
        __syncthreads();
        u32 B0 = sb + (c&1)*15360;
        u32 sA = B0, sB = B0 + 10240;
        #pragma unroll
        for (int ks = 0; ks < 2; ks++) {
            u32 kb = ks*32 + a_kh;
            u32 a0, a1, a2, a3, a4, a5, a6, a7;
            ldsm4(a0, a1, a2, a3, sA + (rb*32 + a_row)*80 + kb);
            ldsm4(a4, a5, a6, a7, sA + (rb*32 + 16 + a_row)*80 + kb);
            u32 kbb = ks*32 + b_kh;
            #pragma unroll
            for (int p = 0; p < 2; p++) {
                u32 b0, b1, b2, b3;
                ldsm4(b0, b1, b2, b3, sB + (cb*32 + p*16 + b_row)*80 + kbb);
                mma_fp16(acc[0][2*p],   a0, a1, a2, a3, b0, b1);
                mma_fp16(acc[1][2*p],   a4, a5, a6, a7, b0, b1);
                mma_fp16(acc[0][2*p+1], a0, a1, a2, a3, b2, b3);
                mma_fp16(acc[1][2*p+1], a4, a5, a6, a7, b2, b3);
            }
        }
        __syncthreads();
    }

    // epilogue: fragments -> smem -> coalesced tanh/combine writes
    float* D = (float*)dynsm;          // 128 x 68 fp32
    #pragma unroll
    for (int ma = 0; ma < 2; ma++) {
        int row = rb*32 + ma*16 + g;
        #pragma unroll
        for (int na = 0; na < 4; na++) {
            int col = cb*32 + na*8 + 2*t;
            *(float2*)&D[row*68 + col]     = make_float2(acc[ma][na][0], acc[ma][na][1]);
            *(float2*)&D[(row+8)*68 + col] = make_float2(acc[ma][na][2], acc[ma][na][3]);
        }
    }
    __syncthreads();
    #pragma unroll
    for (int i = 0; i < 8; i++) {
        int f = tid + 256*i;           // 0..2047
        int r = f >> 4, c4 = f & 15;
        int col = c4*4;
        size_t m = (size_t)(m0 + r);
        int n = (int)(m >> 5);
        int b = (int)(m & 31);
        float4 v = *(const float4*)&D[r*68 + col];
        float4 b4 = *(const float4*)&bc[col];
        float cd0 = fast_tanh(v.x + b4.x);
        float cd1 = fast_tanh(v.y + b4.y);
        float cd2 = fast_tanh(v.z + b4.z);
        float cd3 = fast_tanh(v.w + b4.w);
        float4 z4 = *(const float4*)&g_Z[m*DOUT + col];
        float4 h4 = *(const float4*)&g_X0[m*FF + 64 + col];
        float4 r4 = make_float4((1.f - z4.x)*h4.x + z4.x*cd0,
                                (1.f - z4.y)*h4.y + z4.y*cd1,
                                (1.f - z4.z)*h4.z + z4.z*cd2,
                                (1.f - z4.w)*h4.w + z4.w*cd3);
        *(float4*)&out[(size_t)b*(NN*DOUT) + (size_t)n*DOUT + col] = r4;
    }
}

// ---------------- launch ----------------
extern "C" void kernel_launch(void* const* d_in, const int* in_sizes, int n_in,
                              void* d_out, int out_size) {
    const float* inp = nullptr;
    const float* hx  = nullptr;
    const void*  ei  = nullptr;
    const float* ew  = nullptr;
    const float* Wg  = nullptr;
    const float* Wc  = nullptr;
    const float* bg  = nullptr;
    const float* bc  = nullptr;
    for (int i = 0; i < n_in; i++) {
        switch (in_sizes[i]) {
            case 20480000: if (!inp) inp = (const float*)d_in[i];
                           else      hx  = (const float*)d_in[i]; break;
            case 320000:   ei = d_in[i];                 break;
            case 160000:   ew = (const float*)d_in[i];   break;
            case 49152:    Wg = (const float*)d_in[i];   break;
            case 24576:    Wc = (const float*)d_in[i];   break;
            case 128:      bg = (const float*)d_in[i];   break;
            case 64:       bc = (const float*)d_in[i];   break;
            default: break;
        }
    }
    float* out = (float*)d_out;

    void *pX0, *pRH, *pXp, *pHp;
    cudaGetSymbolAddress(&pX0, g_X0);
    cudaGetSymbolAddress(&pRH, g_RH);
    cudaGetSymbolAddress(&pXp, g_Xp);
    cudaGetSymbolAddress(&pHp, g_Hp);
    float* X0 = (float*)pX0;
    float* RH = (float*)pRH;
    __half* Xp = (__half*)pXp;   // [stage][XPS]
    __half* Hp = (__half*)pHp;

    cudaFuncSetAttribute(k_gates_mma, cudaFuncAttributeMaxDynamicSharedMemorySize, 67584);
    cudaFuncSetAttribute(k_cand_mma,  cudaFuncAttributeMaxDynamicSharedMemorySize, 34816);

    // 1-3: CSR + X0 (+ plane) + weight planes
    k_histbuild<<<HIST_BLKS + NN + WPL_BLKS, 256>>>((const long long*)ei, inp, hx, Wg, Wc);
    k_scanfill<<<1, 1024>>>((const long long*)ei);
    k_fill<<<HIST_BLKS, 256>>>((const long long*)ei, ew);

    // 4-5: first diffusion (fp16 gather; planes only; X2 uses fp32 X0 base)
    dim3 gf(NN, 2);
    k_conv_h<FF><<<gf, 256>>>((const uint4*)(Xp),         nullptr,
                              (uint4*)(Xp + 1*XPS),       1.f, 0);
    k_conv_h<FF><<<gf, 256>>>((const uint4*)(Xp + XPS),   (const float4*)X0,
                              (uint4*)(Xp + 2*XPS),       2.f, 1);

    // 6: gates GEMM -> z, RH (fp32 + plane)
    k_gates_mma<<<MM/128, 256, 67584>>>(bg);

    // 7-8: second diffusion on RH (fp16 gather; D2 uses fp32 RH base)
    dim3 gh(NN, 1);
    k_conv_h<DOUT><<<gh, 256>>>((const uint4*)(Hp),       nullptr,
                                (uint4*)(Hp + 1*HPS),     1.f, 0);
    k_conv_h<DOUT><<<gh, 256>>>((const uint4*)(Hp + HPS), (const float4*)RH,
                                (uint4*)(Hp + 2*HPS),     2.f, 1);

    // 9: candidate GEMM + combine + transpose
    k_cand_mma<<<MM/128, 256, 34816>>>(bc, out);
}